// round 1
// baseline (speedup 1.0000x reference)
#include <cuda_runtime.h>
#include <math.h>

#define D_MODEL 512
#define NH      8
#define DK      64
#define BATCH   4
#define SEQ     2048
#define MTOT    (BATCH * SEQ)   // 8192

// Scratch (allocation-free rule: __device__ globals)
__device__ float g_Qh[(size_t)BATCH * NH * SEQ * DK];
__device__ float g_Kh[(size_t)BATCH * NH * SEQ * DK];
__device__ float g_Vh[(size_t)BATCH * NH * SEQ * DK];
__device__ float g_O [(size_t)MTOT * D_MODEL];

// ---------------------------------------------------------------------------
// GEMM: Y = X @ W^T + b.  X:[M,512] row-major, W:[512,512] row-major (so B
// operand is W[n][k], K-contiguous like A).  head_layout=1 writes [B,H,S,DK].
// BM=BN=128, BK=16, 256 threads, 8x8 microtile per thread.
// ---------------------------------------------------------------------------
#define BM 128
#define BN 128
#define BK 16

__global__ __launch_bounds__(256)
void gemm_bias_kernel(const float* __restrict__ A,
                      const float* __restrict__ W,
                      const float* __restrict__ bias,
                      float* __restrict__ Y,
                      int head_layout)
{
    __shared__ float As[BK][BM];
    __shared__ float Bs[BK][BN];

    const int K = D_MODEL;
    const int tid = threadIdx.x;
    const int tx = tid & 15;        // 0..15 -> col groups of 8
    const int ty = tid >> 4;        // 0..15 -> row groups of 8
    const int m0 = blockIdx.y * BM;
    const int n0 = blockIdx.x * BN;

    float acc[8][8];
#pragma unroll
    for (int i = 0; i < 8; i++)
#pragma unroll
        for (int j = 0; j < 8; j++) acc[i][j] = 0.0f;

    for (int k0 = 0; k0 < K; k0 += BK) {
        // Load tiles: 128 rows x 16 cols each = 512 float4; 2 per thread per matrix
#pragma unroll
        for (int l = 0; l < 2; l++) {
            int v   = tid + l * 256;    // 0..511
            int row = v >> 2;           // 0..127
            int c4  = v & 3;            // 0..3
            float4 a = *(const float4*)(A + (size_t)(m0 + row) * K + k0 + c4 * 4);
            As[c4 * 4 + 0][row] = a.x;
            As[c4 * 4 + 1][row] = a.y;
            As[c4 * 4 + 2][row] = a.z;
            As[c4 * 4 + 3][row] = a.w;
            float4 b = *(const float4*)(W + (size_t)(n0 + row) * K + k0 + c4 * 4);
            Bs[c4 * 4 + 0][row] = b.x;
            Bs[c4 * 4 + 1][row] = b.y;
            Bs[c4 * 4 + 2][row] = b.z;
            Bs[c4 * 4 + 3][row] = b.w;
        }
        __syncthreads();

#pragma unroll
        for (int kk = 0; kk < BK; kk++) {
            float4 a0 = *(const float4*)(&As[kk][ty * 8]);
            float4 a1 = *(const float4*)(&As[kk][ty * 8 + 4]);
            float4 b0 = *(const float4*)(&Bs[kk][tx * 8]);
            float4 b1 = *(const float4*)(&Bs[kk][tx * 8 + 4]);
            float ra[8] = {a0.x, a0.y, a0.z, a0.w, a1.x, a1.y, a1.z, a1.w};
            float rb[8] = {b0.x, b0.y, b0.z, b0.w, b1.x, b1.y, b1.z, b1.w};
#pragma unroll
            for (int i = 0; i < 8; i++)
#pragma unroll
                for (int j = 0; j < 8; j++)
                    acc[i][j] = fmaf(ra[i], rb[j], acc[i][j]);
        }
        __syncthreads();
    }

#pragma unroll
    for (int i = 0; i < 8; i++) {
        int m = m0 + ty * 8 + i;
#pragma unroll
        for (int j = 0; j < 8; j++) {
            int n = n0 + tx * 8 + j;
            float val = acc[i][j] + bias[n];
            if (head_layout) {
                int b = m >> 11;          // m / SEQ
                int s = m & (SEQ - 1);
                int h = n >> 6;           // n / DK
                int d = n & (DK - 1);
                g_dummy_noop:;
                Y[(((size_t)(b * NH + h) * SEQ) + s) * DK + d] = val;
            } else {
                Y[(size_t)m * D_MODEL + n] = val;
            }
        }
    }
}

// ---------------------------------------------------------------------------
// Flash attention, fp32. One thread = one q row; 64 q rows / CTA.
// K/V tiles 32x64 in smem; scores staged in smem so j-loop stays runtime
// (small code, no register array spills).
// ---------------------------------------------------------------------------
#define KT 32

__global__ __launch_bounds__(64)
void attn_kernel(const int* __restrict__ mask)
{
    __shared__ float Ksh[KT][DK];
    __shared__ float Vsh[KT][DK];
    __shared__ float Ssh[64][KT + 1];

    const int tid = threadIdx.x;
    const int b = blockIdx.z;
    const int h = blockIdx.y;
    const int qi = blockIdx.x * 64 + tid;
    const size_t bh = ((size_t)b * NH + h) * SEQ;

    // q row into registers (64 floats)
    float qreg[DK];
    {
        const float* qp = g_Qh + (bh + qi) * DK;
#pragma unroll
        for (int d4 = 0; d4 < 16; d4++) {
            float4 t = *(const float4*)(qp + d4 * 4);
            qreg[4 * d4 + 0] = t.x; qreg[4 * d4 + 1] = t.y;
            qreg[4 * d4 + 2] = t.z; qreg[4 * d4 + 3] = t.w;
        }
    }

    float o[DK];
#pragma unroll
    for (int d = 0; d < DK; d++) o[d] = 0.0f;
    float mrow = -1e30f;
    float lsum = 0.0f;
    const float scale = 0.125f;   // 1/sqrt(64)

    const int* mrow_ptr = mask + (size_t)qi * SEQ;

    for (int k0 = 0; k0 < SEQ; k0 += KT) {
        // cooperative K/V tile load: 2048 floats each, 8 float4 per thread
        const float* kp = g_Kh + (bh + k0) * DK;
        const float* vp = g_Vh + (bh + k0) * DK;
#pragma unroll
        for (int i = 0; i < 8; i++) {
            int v  = tid + i * 64;     // 0..511
            int r  = v >> 4;           // 0..31
            int c4 = v & 15;           // 0..15
            *(float4*)(&Ksh[r][c4 * 4]) = *(const float4*)(kp + r * DK + c4 * 4);
            *(float4*)(&Vsh[r][c4 * 4]) = *(const float4*)(vp + r * DK + c4 * 4);
        }
        __syncthreads();

        // scores for this tile (runtime j loop; Ksh reads broadcast)
        const int* mp = mrow_ptr + k0;
        float mnew = mrow;
        for (int j = 0; j < KT; j++) {
            float a0 = 0.f, a1 = 0.f, a2 = 0.f, a3 = 0.f;
#pragma unroll
            for (int d4 = 0; d4 < 16; d4++) {
                float4 kv = *(const float4*)(&Ksh[j][d4 * 4]);
                a0 = fmaf(qreg[4 * d4 + 0], kv.x, a0);
                a1 = fmaf(qreg[4 * d4 + 1], kv.y, a1);
                a2 = fmaf(qreg[4 * d4 + 2], kv.z, a2);
                a3 = fmaf(qreg[4 * d4 + 3], kv.w, a3);
            }
            float sc = (a0 + a1) + (a2 + a3);
            sc = (mp[j] == 0) ? -1e9f : sc * scale;   // matches reference order
            Ssh[tid][j] = sc;
            mnew = fmaxf(mnew, sc);
        }

        float corr = __expf(mrow - mnew);
        mrow = mnew;
        float psum = 0.0f;
        for (int j = 0; j < KT; j++) {
            float p = __expf(Ssh[tid][j] - mnew);
            Ssh[tid][j] = p;
            psum += p;
        }
        lsum = lsum * corr + psum;

#pragma unroll
        for (int d = 0; d < DK; d++) o[d] *= corr;

        for (int j = 0; j < KT; j++) {
            float p = Ssh[tid][j];
#pragma unroll
            for (int d4 = 0; d4 < 16; d4++) {
                float4 vv = *(const float4*)(&Vsh[j][d4 * 4]);
                o[4 * d4 + 0] = fmaf(p, vv.x, o[4 * d4 + 0]);
                o[4 * d4 + 1] = fmaf(p, vv.y, o[4 * d4 + 1]);
                o[4 * d4 + 2] = fmaf(p, vv.z, o[4 * d4 + 2]);
                o[4 * d4 + 3] = fmaf(p, vv.w, o[4 * d4 + 3]);
            }
        }
        __syncthreads();
    }

    // write in concat layout [B, S, H*DK]
    float inv = 1.0f / lsum;
    float* op = g_O + ((size_t)b * SEQ + qi) * D_MODEL + h * DK;
#pragma unroll
    for (int d4 = 0; d4 < 16; d4++) {
        float4 t;
        t.x = o[4 * d4 + 0] * inv;
        t.y = o[4 * d4 + 1] * inv;
        t.z = o[4 * d4 + 2] * inv;
        t.w = o[4 * d4 + 3] * inv;
        *(float4*)(op + d4 * 4) = t;
    }
}

// ---------------------------------------------------------------------------

extern "C" void kernel_launch(void* const* d_in, const int* in_sizes, int n_in,
                              void* d_out, int out_size)
{
    (void)in_sizes; (void)n_in; (void)out_size;
    const float* q    = (const float*)d_in[0];
    const float* k    = (const float*)d_in[1];
    const float* v    = (const float*)d_in[2];
    const int*   mask = (const int*)  d_in[3];
    const float* Wq   = (const float*)d_in[4];
    const float* bq   = (const float*)d_in[5];
    const float* Wk   = (const float*)d_in[6];
    const float* bk   = (const float*)d_in[7];
    const float* Wv   = (const float*)d_in[8];
    const float* bv   = (const float*)d_in[9];
    const float* Wo   = (const float*)d_in[10];
    const float* bo   = (const float*)d_in[11];
    float* out = (float*)d_out;

    float *Qh, *Kh, *Vh, *O;
    cudaGetSymbolAddress((void**)&Qh, g_Qh);
    cudaGetSymbolAddress((void**)&Kh, g_Kh);
    cudaGetSymbolAddress((void**)&Vh, g_Vh);
    cudaGetSymbolAddress((void**)&O,  g_O);

    dim3 gemm_grid(D_MODEL / BN, MTOT / BM);   // (4, 64)
    gemm_bias_kernel<<<gemm_grid, 256>>>(q, Wq, bq, Qh, 1);
    gemm_bias_kernel<<<gemm_grid, 256>>>(k, Wk, bk, Kh, 1);
    gemm_bias_kernel<<<gemm_grid, 256>>>(v, Wv, bv, Vh, 1);

    dim3 attn_grid(SEQ / 64, NH, BATCH);       // (32, 8, 4)
    attn_kernel<<<attn_grid, 64>>>(mask);

    gemm_bias_kernel<<<gemm_grid, 256>>>(O, Wo, bo, out, 0);
}

// round 3
// speedup vs baseline: 1.3529x; 1.3529x over previous
#include <cuda_runtime.h>
#include <math.h>

#define D_MODEL 512
#define NH      8
#define DK      64
#define BATCH   4
#define SEQ     2048
#define MTOT    (BATCH * SEQ)   // 8192

// Scratch (allocation-free rule: __device__ globals)
__device__ float g_Qh[(size_t)BATCH * NH * SEQ * DK];
__device__ float g_Kh[(size_t)BATCH * NH * SEQ * DK];
__device__ float g_Vh[(size_t)BATCH * NH * SEQ * DK];
__device__ float g_O [(size_t)MTOT * D_MODEL];

// ---------------------------------------------------------------------------
// Packed fp32x2 helpers (sm_100+)
// ---------------------------------------------------------------------------
__device__ __forceinline__ void ffma2(float2& d, float2 a, float2 b) {
    asm("fma.rn.f32x2 %0, %1, %2, %0;"
        : "+l"(reinterpret_cast<unsigned long long&>(d))
        : "l"(reinterpret_cast<const unsigned long long&>(a)),
          "l"(reinterpret_cast<const unsigned long long&>(b)));
}
__device__ __forceinline__ float2 rep2(float a) {
    float2 r;
    asm("mov.b64 %0, {%1, %1};"
        : "=l"(reinterpret_cast<unsigned long long&>(r)) : "f"(a));
    return r;
}

// ---------------------------------------------------------------------------
// GEMM: Y = X @ W^T + b.  X:[M,512], W:[512,512] row-major.
// BM=BN=128, BK=16, 256 threads, 8x8 microtile, f32x2 inner loop.
// head_layout=1 writes [B,H,S,DK].
// ---------------------------------------------------------------------------
#define BM 128
#define BN 128
#define BK 16

__global__ __launch_bounds__(256)
void gemm_bias_kernel(const float* __restrict__ A,
                      const float* __restrict__ W,
                      const float* __restrict__ bias,
                      float* __restrict__ Y,
                      int head_layout)
{
    __shared__ float As[BK][BM];
    __shared__ float Bs[BK][BN];

    const int K = D_MODEL;
    const int tid = threadIdx.x;
    const int tx = tid & 15;        // col group of 8
    const int ty = tid >> 4;        // row group of 8
    const int m0 = blockIdx.y * BM;
    const int n0 = blockIdx.x * BN;

    float2 acc[4][8];
#pragma unroll
    for (int i = 0; i < 4; i++)
#pragma unroll
        for (int j = 0; j < 8; j++) acc[i][j] = make_float2(0.f, 0.f);

    for (int k0 = 0; k0 < K; k0 += BK) {
#pragma unroll
        for (int l = 0; l < 2; l++) {
            int v   = tid + l * 256;    // 0..511
            int row = v >> 2;           // 0..127
            int c4  = v & 3;            // 0..3
            float4 a = *(const float4*)(A + (size_t)(m0 + row) * K + k0 + c4 * 4);
            As[c4 * 4 + 0][row] = a.x;
            As[c4 * 4 + 1][row] = a.y;
            As[c4 * 4 + 2][row] = a.z;
            As[c4 * 4 + 3][row] = a.w;
            float4 b = *(const float4*)(W + (size_t)(n0 + row) * K + k0 + c4 * 4);
            Bs[c4 * 4 + 0][row] = b.x;
            Bs[c4 * 4 + 1][row] = b.y;
            Bs[c4 * 4 + 2][row] = b.z;
            Bs[c4 * 4 + 3][row] = b.w;
        }
        __syncthreads();

#pragma unroll
        for (int kk = 0; kk < BK; kk++) {
            float4 a0 = *(const float4*)(&As[kk][ty * 8]);
            float4 a1 = *(const float4*)(&As[kk][ty * 8 + 4]);
            float4 b0 = *(const float4*)(&Bs[kk][tx * 8]);
            float4 b1 = *(const float4*)(&Bs[kk][tx * 8 + 4]);
            float2 ap[4] = { make_float2(a0.x, a0.y), make_float2(a0.z, a0.w),
                             make_float2(a1.x, a1.y), make_float2(a1.z, a1.w) };
            float  bs[8] = { b0.x, b0.y, b0.z, b0.w, b1.x, b1.y, b1.z, b1.w };
#pragma unroll
            for (int j = 0; j < 8; j++) {
                float2 br = rep2(bs[j]);
#pragma unroll
                for (int i = 0; i < 4; i++)
                    ffma2(acc[i][j], ap[i], br);
            }
        }
        __syncthreads();
    }

#pragma unroll
    for (int ip = 0; ip < 4; ip++) {
#pragma unroll
        for (int half = 0; half < 2; half++) {
            int m = m0 + ty * 8 + 2 * ip + half;
#pragma unroll
            for (int j = 0; j < 8; j++) {
                int n = n0 + tx * 8 + j;
                float v = half ? acc[ip][j].y : acc[ip][j].x;
                float val = v + bias[n];
                if (head_layout) {
                    int b = m >> 11;          // m / SEQ
                    int s = m & (SEQ - 1);
                    int h = n >> 6;           // n / DK
                    int d = n & (DK - 1);
                    Y[(((size_t)(b * NH + h) * SEQ) + s) * DK + d] = val;
                } else {
                    Y[(size_t)m * D_MODEL + n] = val;
                }
            }
        }
    }
}

// ---------------------------------------------------------------------------
// Flash attention, register-tiled. CTA: 128 threads, BQ=64 q rows, 64-key tiles.
// Dynamic smem (68.6 KB > 48 KB static limit).
// ---------------------------------------------------------------------------
#define BQ   64
#define BKT  64
#define QST  68   // padded row stride for transposed Q/K and P^T

// dynamic smem layout (floats)
#define OFF_QS  0
#define OFF_KS  (DK * QST)               // 4352
#define OFF_VS  (2 * DK * QST)           // 8704
#define OFF_PS  (2 * DK * QST + BKT * DK)
#define SMEM_FLOATS (OFF_PS + BKT * QST)
#define ATTN_SMEM_BYTES (SMEM_FLOATS * 4)

__global__ __launch_bounds__(128)
void attn_kernel(const int* __restrict__ mask)
{
    extern __shared__ float sm[];
    float* Qs = sm + OFF_QS;     // Q^T : Qs[d][q]
    float* Ks = sm + OFF_KS;     // K^T : Ks[d][k]
    float* Vs = sm + OFF_VS;     // V   : Vs[k][d]
    float* Ps = sm + OFF_PS;     // P^T : Ps[k][q]  (also mask staging)

    const int tid = threadIdx.x;
    const int tx = tid & 15;
    const int ty = tid >> 4;
    const int b  = blockIdx.z;
    const int h  = blockIdx.y;
    const int qbase = blockIdx.x * BQ;
    const size_t bh = ((size_t)b * NH + h) * SEQ;

    const int r  = tid >> 1;     // cooperative-load row 0..63
    const int hf = tid & 1;      // half of the 64-float row

    // ---- load Q tile transposed into Qs ----
    {
        const float* qp = g_Qh + (bh + qbase + r) * DK + hf * 32;
#pragma unroll
        for (int j = 0; j < 8; j++) {
            float4 t = *(const float4*)(qp + 4 * j);
            int d = hf * 32 + 4 * j;
            Qs[(d + 0) * QST + r] = t.x;
            Qs[(d + 1) * QST + r] = t.y;
            Qs[(d + 2) * QST + r] = t.z;
            Qs[(d + 3) * QST + r] = t.w;
        }
    }

    float2 oacc[4][4];           // [row-pair][col]
#pragma unroll
    for (int i = 0; i < 4; i++)
#pragma unroll
        for (int j = 0; j < 4; j++) oacc[i][j] = make_float2(0.f, 0.f);
    float mrow[8], lsum[8];
#pragma unroll
    for (int i = 0; i < 8; i++) { mrow[i] = -1e30f; lsum[i] = 0.f; }

    for (int k0 = 0; k0 < SEQ; k0 += BKT) {
        __syncthreads();   // prev O-GEMM done with Ks/Vs/Ps

        // ---- cooperative loads: K^T, V, mask tile (into Ps as int) ----
        {
            const float* kp = g_Kh + (bh + k0 + r) * DK + hf * 32;
            const float* vp = g_Vh + (bh + k0 + r) * DK + hf * 32;
            const int*   mp = mask + (size_t)(qbase + r) * SEQ + k0 + hf * 32;
            int* msk = (int*)Ps;
#pragma unroll
            for (int j = 0; j < 8; j++) {
                float4 t = *(const float4*)(kp + 4 * j);
                int d = hf * 32 + 4 * j;
                Ks[(d + 0) * QST + r] = t.x;
                Ks[(d + 1) * QST + r] = t.y;
                Ks[(d + 2) * QST + r] = t.z;
                Ks[(d + 3) * QST + r] = t.w;
            }
#pragma unroll
            for (int j = 0; j < 8; j++)
                *(float4*)(&Vs[r * DK + hf * 32 + 4 * j]) = *(const float4*)(vp + 4 * j);
#pragma unroll
            for (int j = 0; j < 8; j++)
                *(int4*)(&msk[r * BKT + hf * 32 + 4 * j]) = *(const int4*)(mp + 4 * j);
        }
        __syncthreads();

        // ---- S = Q @ K^T  (fragment: 4 row-pairs x 4 cols) ----
        float2 sacc[4][4];
#pragma unroll
        for (int i = 0; i < 4; i++)
#pragma unroll
            for (int j = 0; j < 4; j++) sacc[i][j] = make_float2(0.f, 0.f);

#pragma unroll 8
        for (int d = 0; d < DK; d++) {
            float4 q0 = *(const float4*)(&Qs[d * QST + 8 * ty]);
            float4 q1 = *(const float4*)(&Qs[d * QST + 8 * ty + 4]);
            float4 kv = *(const float4*)(&Ks[d * QST + 4 * tx]);
            float2 ap[4] = { make_float2(q0.x, q0.y), make_float2(q0.z, q0.w),
                             make_float2(q1.x, q1.y), make_float2(q1.z, q1.w) };
            float  kb[4] = { kv.x, kv.y, kv.z, kv.w };
#pragma unroll
            for (int c = 0; c < 4; c++) {
                float2 br = rep2(kb[c]);
#pragma unroll
                for (int i = 0; i < 4; i++)
                    ffma2(sacc[i][c], ap[i], br);
            }
        }

        // ---- mask + online softmax (rows spread over 16 tx lanes) ----
        float p[8][4];
#pragma unroll
        for (int i = 0; i < 8; i++) {
            int4 mv = *(const int4*)(&((const int*)Ps)[(8 * ty + i) * BKT + 4 * tx]);
            float s0 = (i & 1) ? sacc[i >> 1][0].y : sacc[i >> 1][0].x;
            float s1 = (i & 1) ? sacc[i >> 1][1].y : sacc[i >> 1][1].x;
            float s2 = (i & 1) ? sacc[i >> 1][2].y : sacc[i >> 1][2].x;
            float s3 = (i & 1) ? sacc[i >> 1][3].y : sacc[i >> 1][3].x;
            s0 = (mv.x == 0) ? -1e9f : s0 * 0.125f;
            s1 = (mv.y == 0) ? -1e9f : s1 * 0.125f;
            s2 = (mv.z == 0) ? -1e9f : s2 * 0.125f;
            s3 = (mv.w == 0) ? -1e9f : s3 * 0.125f;
            float mx = fmaxf(fmaxf(s0, s1), fmaxf(s2, s3));
#pragma unroll
            for (int off = 8; off >= 1; off >>= 1)
                mx = fmaxf(mx, __shfl_xor_sync(0xffffffffu, mx, off));
            float mnew = fmaxf(mrow[i], mx);
            float corr = __expf(mrow[i] - mnew);
            mrow[i] = mnew;
            float p0 = __expf(s0 - mnew);
            float p1 = __expf(s1 - mnew);
            float p2 = __expf(s2 - mnew);
            float p3 = __expf(s3 - mnew);
            float rs = (p0 + p1) + (p2 + p3);
#pragma unroll
            for (int off = 8; off >= 1; off >>= 1)
                rs += __shfl_xor_sync(0xffffffffu, rs, off);
            lsum[i] = lsum[i] * corr + rs;
            if (i & 1) {
                oacc[i >> 1][0].y *= corr; oacc[i >> 1][1].y *= corr;
                oacc[i >> 1][2].y *= corr; oacc[i >> 1][3].y *= corr;
            } else {
                oacc[i >> 1][0].x *= corr; oacc[i >> 1][1].x *= corr;
                oacc[i >> 1][2].x *= corr; oacc[i >> 1][3].x *= corr;
            }
            p[i][0] = p0; p[i][1] = p1; p[i][2] = p2; p[i][3] = p3;
        }
        __syncthreads();   // everyone done reading mask from Ps

        // ---- write P^T to Ps ----
#pragma unroll
        for (int c = 0; c < 4; c++) {
            int k = 4 * tx + c;
            *(float4*)(&Ps[k * QST + 8 * ty]) =
                make_float4(p[0][c], p[1][c], p[2][c], p[3][c]);
            *(float4*)(&Ps[k * QST + 8 * ty + 4]) =
                make_float4(p[4][c], p[5][c], p[6][c], p[7][c]);
        }
        __syncthreads();

        // ---- O += P @ V ----
#pragma unroll 8
        for (int k = 0; k < BKT; k++) {
            float4 p0 = *(const float4*)(&Ps[k * QST + 8 * ty]);
            float4 p1 = *(const float4*)(&Ps[k * QST + 8 * ty + 4]);
            float4 vv = *(const float4*)(&Vs[k * DK + 4 * tx]);
            float2 ap[4] = { make_float2(p0.x, p0.y), make_float2(p0.z, p0.w),
                             make_float2(p1.x, p1.y), make_float2(p1.z, p1.w) };
            float  vb[4] = { vv.x, vv.y, vv.z, vv.w };
#pragma unroll
            for (int c = 0; c < 4; c++) {
                float2 br = rep2(vb[c]);
#pragma unroll
                for (int i = 0; i < 4; i++)
                    ffma2(oacc[i][c], ap[i], br);
            }
        }
    }

    // ---- epilogue: normalize, write concat layout [B, S, H*DK] ----
#pragma unroll
    for (int i = 0; i < 8; i++) {
        float inv = 1.0f / lsum[i];
        int q = qbase + 8 * ty + i;
        float v0 = (i & 1) ? oacc[i >> 1][0].y : oacc[i >> 1][0].x;
        float v1 = (i & 1) ? oacc[i >> 1][1].y : oacc[i >> 1][1].x;
        float v2 = (i & 1) ? oacc[i >> 1][2].y : oacc[i >> 1][2].x;
        float v3 = (i & 1) ? oacc[i >> 1][3].y : oacc[i >> 1][3].x;
        *(float4*)(&g_O[((size_t)b * SEQ + q) * D_MODEL + h * DK + 4 * tx]) =
            make_float4(v0 * inv, v1 * inv, v2 * inv, v3 * inv);
    }
}

// ---------------------------------------------------------------------------

extern "C" void kernel_launch(void* const* d_in, const int* in_sizes, int n_in,
                              void* d_out, int out_size)
{
    (void)in_sizes; (void)n_in; (void)out_size;
    const float* q    = (const float*)d_in[0];
    const float* k    = (const float*)d_in[1];
    const float* v    = (const float*)d_in[2];
    const int*   mask = (const int*)  d_in[3];
    const float* Wq   = (const float*)d_in[4];
    const float* bq   = (const float*)d_in[5];
    const float* Wk   = (const float*)d_in[6];
    const float* bk   = (const float*)d_in[7];
    const float* Wv   = (const float*)d_in[8];
    const float* bv   = (const float*)d_in[9];
    const float* Wo   = (const float*)d_in[10];
    const float* bo   = (const float*)d_in[11];
    float* out = (float*)d_out;

    float *Qh, *Kh, *Vh, *O;
    cudaGetSymbolAddress((void**)&Qh, g_Qh);
    cudaGetSymbolAddress((void**)&Kh, g_Kh);
    cudaGetSymbolAddress((void**)&Vh, g_Vh);
    cudaGetSymbolAddress((void**)&O,  g_O);

    // allow >48KB dynamic smem for the attention kernel (attribute set, not an alloc)
    static int smem_cfg_done = 0;
    if (!smem_cfg_done) {
        cudaFuncSetAttribute(attn_kernel,
                             cudaFuncAttributeMaxDynamicSharedMemorySize,
                             ATTN_SMEM_BYTES);
        smem_cfg_done = 1;
    }

    dim3 gemm_grid(D_MODEL / BN, MTOT / BM);   // (4, 64)
    gemm_bias_kernel<<<gemm_grid, 256>>>(q, Wq, bq, Qh, 1);
    gemm_bias_kernel<<<gemm_grid, 256>>>(k, Wk, bk, Kh, 1);
    gemm_bias_kernel<<<gemm_grid, 256>>>(v, Wv, bv, Vh, 1);

    dim3 attn_grid(SEQ / BQ, NH, BATCH);       // (32, 8, 4)
    attn_kernel<<<attn_grid, 128, ATTN_SMEM_BYTES>>>(mask);

    gemm_bias_kernel<<<gemm_grid, 256>>>(O, Wo, bo, out, 0);
}

// round 5
// speedup vs baseline: 1.9027x; 1.4063x over previous
#include <cuda_runtime.h>
#include <cuda_bf16.h>
#include <math.h>
#include <stdint.h>

#define D_MODEL 512
#define NH      8
#define DK      64
#define BATCH   4
#define SEQ     2048
#define MTOT    (BATCH * SEQ)   // 8192

// Scratch (allocation-free rule: __device__ globals)
__device__ float g_Qh[(size_t)BATCH * NH * SEQ * DK];
__device__ float g_Kh[(size_t)BATCH * NH * SEQ * DK];
__device__ float g_Vh[(size_t)BATCH * NH * SEQ * DK];
__device__ float g_O [(size_t)MTOT * D_MODEL];

// ---------------------------------------------------------------------------
// Packed fp32x2 helpers (sm_100+) for the projection GEMMs
// ---------------------------------------------------------------------------
__device__ __forceinline__ void ffma2(float2& d, float2 a, float2 b) {
    asm("fma.rn.f32x2 %0, %1, %2, %0;"
        : "+l"(reinterpret_cast<unsigned long long&>(d))
        : "l"(reinterpret_cast<const unsigned long long&>(a)),
          "l"(reinterpret_cast<const unsigned long long&>(b)));
}
__device__ __forceinline__ float2 rep2(float a) {
    float2 r;
    asm("mov.b64 %0, {%1, %1};"
        : "=l"(reinterpret_cast<unsigned long long&>(r)) : "f"(a));
    return r;
}

// ---------------------------------------------------------------------------
// bf16 pack / split helpers
// pack2(e0,e1): e0 -> low half, e1 -> high half
// ---------------------------------------------------------------------------
__device__ __forceinline__ unsigned pack2(float e0, float e1) {
    unsigned r;
    asm("cvt.rn.bf16x2.f32 %0, %1, %2;" : "=r"(r) : "f"(e1), "f"(e0));
    return r;
}
__device__ __forceinline__ void split2(float x0, float x1,
                                       unsigned& hi, unsigned& lo) {
    hi = pack2(x0, x1);
    float h0 = __uint_as_float(hi << 16);
    float h1 = __uint_as_float(hi & 0xffff0000u);
    lo = pack2(x0 - h0, x1 - h1);
}

// m16n8k16 bf16 MMA, D += A*B (accumulate in place)
__device__ __forceinline__ void mma_bf16(float c[4], const unsigned a[4],
                                         unsigned b0, unsigned b1) {
    asm("mma.sync.aligned.m16n8k16.row.col.f32.bf16.bf16.f32 "
        "{%0,%1,%2,%3}, {%4,%5,%6,%7}, {%8,%9}, {%0,%1,%2,%3};"
        : "+f"(c[0]), "+f"(c[1]), "+f"(c[2]), "+f"(c[3])
        : "r"(a[0]), "r"(a[1]), "r"(a[2]), "r"(a[3]), "r"(b0), "r"(b1));
}

// ---------------------------------------------------------------------------
// GEMM: Y = X @ W^T + b (f32x2 SIMT).  head_layout=1 writes [B,H,S,DK].
// ---------------------------------------------------------------------------
#define BM 128
#define BN 128
#define BK 16

__global__ __launch_bounds__(256)
void gemm_bias_kernel(const float* __restrict__ A,
                      const float* __restrict__ W,
                      const float* __restrict__ bias,
                      float* __restrict__ Y,
                      int head_layout)
{
    __shared__ float As[BK][BM];
    __shared__ float Bs[BK][BN];

    const int K = D_MODEL;
    const int tid = threadIdx.x;
    const int tx = tid & 15;
    const int ty = tid >> 4;
    const int m0 = blockIdx.y * BM;
    const int n0 = blockIdx.x * BN;

    float2 acc[4][8];
#pragma unroll
    for (int i = 0; i < 4; i++)
#pragma unroll
        for (int j = 0; j < 8; j++) acc[i][j] = make_float2(0.f, 0.f);

    for (int k0 = 0; k0 < K; k0 += BK) {
#pragma unroll
        for (int l = 0; l < 2; l++) {
            int v   = tid + l * 256;
            int row = v >> 2;
            int c4  = v & 3;
            float4 a = *(const float4*)(A + (size_t)(m0 + row) * K + k0 + c4 * 4);
            As[c4 * 4 + 0][row] = a.x;
            As[c4 * 4 + 1][row] = a.y;
            As[c4 * 4 + 2][row] = a.z;
            As[c4 * 4 + 3][row] = a.w;
            float4 b = *(const float4*)(W + (size_t)(n0 + row) * K + k0 + c4 * 4);
            Bs[c4 * 4 + 0][row] = b.x;
            Bs[c4 * 4 + 1][row] = b.y;
            Bs[c4 * 4 + 2][row] = b.z;
            Bs[c4 * 4 + 3][row] = b.w;
        }
        __syncthreads();

#pragma unroll
        for (int kk = 0; kk < BK; kk++) {
            float4 a0 = *(const float4*)(&As[kk][ty * 8]);
            float4 a1 = *(const float4*)(&As[kk][ty * 8 + 4]);
            float4 b0 = *(const float4*)(&Bs[kk][tx * 8]);
            float4 b1 = *(const float4*)(&Bs[kk][tx * 8 + 4]);
            float2 ap[4] = { make_float2(a0.x, a0.y), make_float2(a0.z, a0.w),
                             make_float2(a1.x, a1.y), make_float2(a1.z, a1.w) };
            float  bs[8] = { b0.x, b0.y, b0.z, b0.w, b1.x, b1.y, b1.z, b1.w };
#pragma unroll
            for (int j = 0; j < 8; j++) {
                float2 br = rep2(bs[j]);
#pragma unroll
                for (int i = 0; i < 4; i++)
                    ffma2(acc[i][j], ap[i], br);
            }
        }
        __syncthreads();
    }

#pragma unroll
    for (int ip = 0; ip < 4; ip++) {
#pragma unroll
        for (int half = 0; half < 2; half++) {
            int m = m0 + ty * 8 + 2 * ip + half;
#pragma unroll
            for (int j = 0; j < 8; j++) {
                int n = n0 + tx * 8 + j;
                float v = half ? acc[ip][j].y : acc[ip][j].x;
                float val = v + bias[n];
                if (head_layout) {
                    int b = m >> 11;
                    int s = m & (SEQ - 1);
                    int h = n >> 6;
                    int d = n & (DK - 1);
                    Y[(((size_t)(b * NH + h) * SEQ) + s) * DK + d] = val;
                } else {
                    Y[(size_t)m * D_MODEL + n] = val;
                }
            }
        }
    }
}

// ---------------------------------------------------------------------------
// Flash attention on tensor cores: mma.sync m16n8k16 bf16, 3-term split.
// CTA = 128 threads (4 warps); BQ=64 q rows (warp w owns rows w*16..w*16+15),
// key tiles of 64. K staged bf16 hi/lo [key][d]; V staged transposed [d][key].
// ---------------------------------------------------------------------------
#define BQ   64
#define BKT  64
#define KST  72      // u16 row stride for bf16 tiles (pad vs bank conflicts)
#define MST  68      // int row stride for mask tile

#define SM_KHI   0
#define SM_KLO   (64 * KST)            // u16 index
#define SM_VTHI  (2 * 64 * KST)
#define SM_VTLO  (3 * 64 * KST)
#define SM_BF16_BYTES (4 * 64 * KST * 2)                 // 36864
#define ATTN_SMEM_BYTES (SM_BF16_BYTES + 64 * MST * 4)   // 54272

__global__ __launch_bounds__(128)
void attn_kernel(const int* __restrict__ mask)
{
    extern __shared__ char smraw[];
    uint16_t* Khi  = (uint16_t*)smraw + SM_KHI;
    uint16_t* Klo  = (uint16_t*)smraw + SM_KLO;
    uint16_t* Vthi = (uint16_t*)smraw + SM_VTHI;
    uint16_t* Vtlo = (uint16_t*)smraw + SM_VTLO;
    int*      Msk  = (int*)(smraw + SM_BF16_BYTES);

    const int tid  = threadIdx.x;
    const int w    = tid >> 5;
    const int lane = tid & 31;
    const int g    = lane >> 2;    // 0..7
    const int t    = lane & 3;     // 0..3
    const int b    = blockIdx.z;
    const int h    = blockIdx.y;
    const int qbase = blockIdx.x * BQ;
    const size_t bh = ((size_t)b * NH + h) * SEQ;

    // ---- Q fragments (bf16 hi/lo) into registers, once ----
    unsigned ah[4][4], al[4][4];
    {
        const float* q0p = g_Qh + (bh + qbase + w * 16 + g) * DK;
        const float* q1p = q0p + 8 * DK;
#pragma unroll
        for (int kc = 0; kc < 4; kc++) {
            int d = kc * 16 + t * 2;
            split2(q0p[d],     q0p[d + 1], ah[kc][0], al[kc][0]);
            split2(q1p[d],     q1p[d + 1], ah[kc][1], al[kc][1]);
            split2(q0p[d + 8], q0p[d + 9], ah[kc][2], al[kc][2]);
            split2(q1p[d + 8], q1p[d + 9], ah[kc][3], al[kc][3]);
        }
    }

    float o[8][4];
#pragma unroll
    for (int nt = 0; nt < 8; nt++)
#pragma unroll
        for (int i = 0; i < 4; i++) o[nt][i] = 0.f;
    float mrow0 = -1e30f, mrow1 = -1e30f, lsum0 = 0.f, lsum1 = 0.f;

    const int r  = tid >> 1;     // staging row 0..63
    const int hf = tid & 1;

    for (int k0 = 0; k0 < SEQ; k0 += BKT) {
        __syncthreads();   // previous iteration done reading smem

        // ---- stage K (hi/lo), V transposed (hi/lo), mask tile ----
        {
            const float* kp = g_Kh + (bh + k0 + r) * DK + hf * 32;
            const float* vp = g_Vh + (bh + k0 + r) * DK + hf * 32;
            const int*   mp = mask + (size_t)(qbase + r) * SEQ + k0 + hf * 32;
#pragma unroll
            for (int j = 0; j < 8; j++) {
                int d = hf * 32 + 4 * j;
                float4 kv = *(const float4*)(kp + 4 * j);
                unsigned h01, l01, h23, l23;
                split2(kv.x, kv.y, h01, l01);
                split2(kv.z, kv.w, h23, l23);
                *(unsigned*)&Khi[r * KST + d]     = h01;
                *(unsigned*)&Khi[r * KST + d + 2] = h23;
                *(unsigned*)&Klo[r * KST + d]     = l01;
                *(unsigned*)&Klo[r * KST + d + 2] = l23;

                float4 vv = *(const float4*)(vp + 4 * j);
                float xs[4] = {vv.x, vv.y, vv.z, vv.w};
#pragma unroll
                for (int i = 0; i < 4; i++) {
                    __nv_bfloat16 bhv = __float2bfloat16(xs[i]);
                    float res = xs[i] - __bfloat162float(bhv);
                    __nv_bfloat16 blv = __float2bfloat16(res);
                    Vthi[(d + i) * KST + r] = *(uint16_t*)&bhv;
                    Vtlo[(d + i) * KST + r] = *(uint16_t*)&blv;
                }

                *(int4*)&Msk[r * MST + d] = *(const int4*)(mp + 4 * j);
            }
        }
        __syncthreads();

        // ---- S = Q @ K^T (3-term bf16 split) ----
        float s[8][4];
#pragma unroll
        for (int nt = 0; nt < 8; nt++) {
            float c[4] = {0.f, 0.f, 0.f, 0.f};
#pragma unroll
            for (int kc = 0; kc < 4; kc++) {
                int base = (nt * 8 + g) * KST + kc * 16 + t * 2;
                unsigned bh0 = *(unsigned*)&Khi[base];
                unsigned bh1 = *(unsigned*)&Khi[base + 8];
                unsigned bl0 = *(unsigned*)&Klo[base];
                unsigned bl1 = *(unsigned*)&Klo[base + 8];
                mma_bf16(c, al[kc], bh0, bh1);
                mma_bf16(c, ah[kc], bl0, bl1);
                mma_bf16(c, ah[kc], bh0, bh1);
            }
            s[nt][0] = c[0]; s[nt][1] = c[1]; s[nt][2] = c[2]; s[nt][3] = c[3];
        }

        // ---- mask + scale + online softmax ----
        const int* mr0 = Msk + (w * 16 + g) * MST;
        const int* mr1 = mr0 + 8 * MST;
        float rmax0 = -1e30f, rmax1 = -1e30f;
#pragma unroll
        for (int nt = 0; nt < 8; nt++) {
            int2 m01 = *(const int2*)(mr0 + nt * 8 + t * 2);
            int2 m23 = *(const int2*)(mr1 + nt * 8 + t * 2);
            s[nt][0] = (m01.x == 0) ? -1e9f : s[nt][0] * 0.125f;
            s[nt][1] = (m01.y == 0) ? -1e9f : s[nt][1] * 0.125f;
            s[nt][2] = (m23.x == 0) ? -1e9f : s[nt][2] * 0.125f;
            s[nt][3] = (m23.y == 0) ? -1e9f : s[nt][3] * 0.125f;
            rmax0 = fmaxf(rmax0, fmaxf(s[nt][0], s[nt][1]));
            rmax1 = fmaxf(rmax1, fmaxf(s[nt][2], s[nt][3]));
        }
        rmax0 = fmaxf(rmax0, __shfl_xor_sync(0xffffffffu, rmax0, 1));
        rmax0 = fmaxf(rmax0, __shfl_xor_sync(0xffffffffu, rmax0, 2));
        rmax1 = fmaxf(rmax1, __shfl_xor_sync(0xffffffffu, rmax1, 1));
        rmax1 = fmaxf(rmax1, __shfl_xor_sync(0xffffffffu, rmax1, 2));

        float mnew0 = fmaxf(mrow0, rmax0);
        float mnew1 = fmaxf(mrow1, rmax1);
        float corr0 = __expf(mrow0 - mnew0);
        float corr1 = __expf(mrow1 - mnew1);
        mrow0 = mnew0; mrow1 = mnew1;

        float sum0 = 0.f, sum1 = 0.f;
#pragma unroll
        for (int nt = 0; nt < 8; nt++) {
            s[nt][0] = __expf(s[nt][0] - mnew0);
            s[nt][1] = __expf(s[nt][1] - mnew0);
            s[nt][2] = __expf(s[nt][2] - mnew1);
            s[nt][3] = __expf(s[nt][3] - mnew1);
            sum0 += s[nt][0] + s[nt][1];
            sum1 += s[nt][2] + s[nt][3];
        }
        sum0 += __shfl_xor_sync(0xffffffffu, sum0, 1);
        sum0 += __shfl_xor_sync(0xffffffffu, sum0, 2);
        sum1 += __shfl_xor_sync(0xffffffffu, sum1, 1);
        sum1 += __shfl_xor_sync(0xffffffffu, sum1, 2);
        lsum0 = lsum0 * corr0 + sum0;
        lsum1 = lsum1 * corr1 + sum1;

#pragma unroll
        for (int nt = 0; nt < 8; nt++) {
            o[nt][0] *= corr0; o[nt][1] *= corr0;
            o[nt][2] *= corr1; o[nt][3] *= corr1;
        }

        // ---- O += P @ V  (P frag = S C-frag layout; split per kc) ----
#pragma unroll
        for (int kc = 0; kc < 4; kc++) {
            unsigned ph[4], pl[4];
            split2(s[2 * kc][0],     s[2 * kc][1],     ph[0], pl[0]);
            split2(s[2 * kc][2],     s[2 * kc][3],     ph[1], pl[1]);
            split2(s[2 * kc + 1][0], s[2 * kc + 1][1], ph[2], pl[2]);
            split2(s[2 * kc + 1][2], s[2 * kc + 1][3], ph[3], pl[3]);
#pragma unroll
            for (int nt = 0; nt < 8; nt++) {
                int base = (nt * 8 + g) * KST + kc * 16 + t * 2;
                unsigned vh0 = *(unsigned*)&Vthi[base];
                unsigned vh1 = *(unsigned*)&Vthi[base + 8];
                unsigned vl0 = *(unsigned*)&Vtlo[base];
                unsigned vl1 = *(unsigned*)&Vtlo[base + 8];
                mma_bf16(o[nt], pl, vh0, vh1);
                mma_bf16(o[nt], ph, vl0, vl1);
                mma_bf16(o[nt], ph, vh0, vh1);
            }
        }
    }

    // ---- epilogue: normalize, write concat layout [B, S, H*DK] ----
    float inv0 = 1.0f / lsum0;
    float inv1 = 1.0f / lsum1;
    int q0 = qbase + w * 16 + g;
    float* op0 = g_O + ((size_t)b * SEQ + q0) * D_MODEL + h * DK;
    float* op1 = op0 + 8 * (size_t)D_MODEL;
#pragma unroll
    for (int nt = 0; nt < 8; nt++) {
        *(float2*)(op0 + nt * 8 + t * 2) = make_float2(o[nt][0] * inv0, o[nt][1] * inv0);
        *(float2*)(op1 + nt * 8 + t * 2) = make_float2(o[nt][2] * inv1, o[nt][3] * inv1);
    }
}

// ---------------------------------------------------------------------------

extern "C" void kernel_launch(void* const* d_in, const int* in_sizes, int n_in,
                              void* d_out, int out_size)
{
    (void)in_sizes; (void)n_in; (void)out_size;
    const float* q    = (const float*)d_in[0];
    const float* k    = (const float*)d_in[1];
    const float* v    = (const float*)d_in[2];
    const int*   mask = (const int*)  d_in[3];
    const float* Wq   = (const float*)d_in[4];
    const float* bq   = (const float*)d_in[5];
    const float* Wk   = (const float*)d_in[6];
    const float* bk   = (const float*)d_in[7];
    const float* Wv   = (const float*)d_in[8];
    const float* bv   = (const float*)d_in[9];
    const float* Wo   = (const float*)d_in[10];
    const float* bo   = (const float*)d_in[11];
    float* out = (float*)d_out;

    float *Qh, *Kh, *Vh, *O;
    cudaGetSymbolAddress((void**)&Qh, g_Qh);
    cudaGetSymbolAddress((void**)&Kh, g_Kh);
    cudaGetSymbolAddress((void**)&Vh, g_Vh);
    cudaGetSymbolAddress((void**)&O,  g_O);

    // No static guard (harness forbids them); attribute set is idempotent,
    // not stream-ordered, and safe under graph capture.
    cudaFuncSetAttribute(attn_kernel,
                         cudaFuncAttributeMaxDynamicSharedMemorySize,
                         ATTN_SMEM_BYTES);

    dim3 gemm_grid(D_MODEL / BN, MTOT / BM);   // (4, 64)
    gemm_bias_kernel<<<gemm_grid, 256>>>(q, Wq, bq, Qh, 1);
    gemm_bias_kernel<<<gemm_grid, 256>>>(k, Wk, bk, Kh, 1);
    gemm_bias_kernel<<<gemm_grid, 256>>>(v, Wv, bv, Vh, 1);

    dim3 attn_grid(SEQ / BQ, NH, BATCH);       // (32, 8, 4)
    attn_kernel<<<attn_grid, 128, ATTN_SMEM_BYTES>>>(mask);

    gemm_bias_kernel<<<gemm_grid, 256>>>(O, Wo, bo, out, 0);
}

// round 7
// speedup vs baseline: 2.7651x; 1.4533x over previous
#include <cuda_runtime.h>
#include <cuda_bf16.h>
#include <math.h>
#include <stdint.h>

#define D_MODEL 512
#define NH      8
#define DK      64
#define BATCH   4
#define SEQ     2048
#define MTOT    (BATCH * SEQ)   // 8192

// Scratch (allocation-free rule: __device__ globals)
__device__ float g_Qh[(size_t)BATCH * NH * SEQ * DK];
__device__ float g_Kh[(size_t)BATCH * NH * SEQ * DK];
__device__ float g_Vh[(size_t)BATCH * NH * SEQ * DK];
__device__ float g_O [(size_t)MTOT * D_MODEL];

// ---------------------------------------------------------------------------
// bf16 helpers: pack2(e0,e1): e0 -> low half, e1 -> high half
// ---------------------------------------------------------------------------
__device__ __forceinline__ unsigned pack2(float e0, float e1) {
    unsigned r;
    asm("cvt.rn.bf16x2.f32 %0, %1, %2;" : "=r"(r) : "f"(e1), "f"(e0));
    return r;
}
__device__ __forceinline__ void split2(float x0, float x1,
                                       unsigned& hi, unsigned& lo) {
    hi = pack2(x0, x1);
    float h0 = __uint_as_float(hi << 16);
    float h1 = __uint_as_float(hi & 0xffff0000u);
    lo = pack2(x0 - h0, x1 - h1);
}

// m16n8k16 bf16 MMA, D += A*B
__device__ __forceinline__ void mma_bf16(float c[4], const unsigned a[4],
                                         unsigned b0, unsigned b1) {
    asm("mma.sync.aligned.m16n8k16.row.col.f32.bf16.bf16.f32 "
        "{%0,%1,%2,%3}, {%4,%5,%6,%7}, {%8,%9}, {%0,%1,%2,%3};"
        : "+f"(c[0]), "+f"(c[1]), "+f"(c[2]), "+f"(c[3])
        : "r"(a[0]), "r"(a[1]), "r"(a[2]), "r"(a[3]), "r"(b0), "r"(b1));
}

__device__ __forceinline__ void ldsm_x4(unsigned& r0, unsigned& r1,
                                        unsigned& r2, unsigned& r3,
                                        unsigned addr) {
    asm volatile("ldmatrix.sync.aligned.m8n8.x4.shared.b16 {%0,%1,%2,%3}, [%4];"
                 : "=r"(r0), "=r"(r1), "=r"(r2), "=r"(r3) : "r"(addr));
}
__device__ __forceinline__ void ldsm_x4_t(unsigned& r0, unsigned& r1,
                                          unsigned& r2, unsigned& r3,
                                          unsigned addr) {
    asm volatile("ldmatrix.sync.aligned.m8n8.x4.trans.shared.b16 {%0,%1,%2,%3}, [%4];"
                 : "=r"(r0), "=r"(r1), "=r"(r2), "=r"(r3) : "r"(addr));
}

// ---------------------------------------------------------------------------
// Projection GEMM on tensor cores: Y = X @ W^T + b, 3-term bf16 split.
// Tile 128(M) x 64(N) x 32(K-step). 128 threads / 4 warps, warp = 64m x 32n.
// ---------------------------------------------------------------------------
#define PBM  128
#define PBN  64
#define PBK  32
#define PKST 40   // u16 row stride (32 + 8 pad); 80B rows -> LDSM conflict-free

__global__ __launch_bounds__(128)
void proj_kernel(const float* __restrict__ A,
                 const float* __restrict__ W,
                 const float* __restrict__ bias,
                 float* __restrict__ Y,
                 int head_layout)
{
    __shared__ uint16_t Asm[2 * PBM * PKST];   // [hi | lo]
    __shared__ uint16_t Bsm[2 * PBN * PKST];

    const int tid  = threadIdx.x;
    const int lane = tid & 31;
    const int w    = tid >> 5;
    const int wm   = w & 1;       // m 64-block
    const int wn   = w >> 1;      // n 32-block
    const int g    = lane >> 2;
    const int t    = lane & 3;
    const int m0   = blockIdx.y * PBM;
    const int n0   = blockIdx.x * PBN;

    float c[4][4][4];
#pragma unroll
    for (int i = 0; i < 4; i++)
#pragma unroll
        for (int j = 0; j < 4; j++)
#pragma unroll
            for (int q = 0; q < 4; q++) c[i][j][q] = 0.f;

    // per-lane LDSM base offsets (u16 units)
    const unsigned a_lane = (wm * 64 + ((lane >> 3) & 1) * 8 + (lane & 7)) * PKST
                          + (lane >> 4) * 8;
    const unsigned b_lane = (wn * 32 + (lane & 7)) * PKST
                          + ((lane >> 3) & 1) * 8
                          + (lane >> 4) * (PBN * PKST);
    const unsigned a_hi = (unsigned)__cvta_generic_to_shared(Asm) + 2 * a_lane;
    const unsigned a_lo = a_hi + 2 * (PBM * PKST);
    const unsigned b_ad = (unsigned)__cvta_generic_to_shared(Bsm) + 2 * b_lane;

    for (int k0 = 0; k0 < D_MODEL; k0 += PBK) {
        __syncthreads();
        // ---- stage A (128x32) and B=W (64x32) as bf16 hi/lo ----
#pragma unroll
        for (int l = 0; l < 8; l++) {
            int v = l * 128 + tid;       // 0..1023
            int row = v >> 3;            // 0..127
            int c4  = v & 7;             // 0..7
            float4 a = *(const float4*)(A + (size_t)(m0 + row) * D_MODEL + k0 + c4 * 4);
            unsigned h01, l01, h23, l23;
            split2(a.x, a.y, h01, l01);
            split2(a.z, a.w, h23, l23);
            *(uint2*)&Asm[row * PKST + c4 * 4]             = make_uint2(h01, h23);
            *(uint2*)&Asm[PBM * PKST + row * PKST + c4 * 4] = make_uint2(l01, l23);
        }
#pragma unroll
        for (int l = 0; l < 4; l++) {
            int v = l * 128 + tid;       // 0..511
            int row = v >> 3;            // 0..63
            int c4  = v & 7;
            float4 b = *(const float4*)(W + (size_t)(n0 + row) * D_MODEL + k0 + c4 * 4);
            unsigned h01, l01, h23, l23;
            split2(b.x, b.y, h01, l01);
            split2(b.z, b.w, h23, l23);
            *(uint2*)&Bsm[row * PKST + c4 * 4]             = make_uint2(h01, h23);
            *(uint2*)&Bsm[PBN * PKST + row * PKST + c4 * 4] = make_uint2(l01, l23);
        }
        __syncthreads();

#pragma unroll
        for (int kk = 0; kk < 2; kk++) {
            unsigned ah[4][4], al[4][4];
#pragma unroll
            for (int mt = 0; mt < 4; mt++) {
                unsigned off = 2 * (mt * 16 * PKST + kk * 16);
                ldsm_x4(ah[mt][0], ah[mt][1], ah[mt][2], ah[mt][3], a_hi + off);
                ldsm_x4(al[mt][0], al[mt][1], al[mt][2], al[mt][3], a_lo + off);
            }
#pragma unroll
            for (int nt = 0; nt < 4; nt++) {
                unsigned bh0, bh1, bl0, bl1;
                ldsm_x4(bh0, bh1, bl0, bl1,
                        b_ad + 2 * (nt * 8 * PKST + kk * 16));
#pragma unroll
                for (int mt = 0; mt < 4; mt++) {
                    mma_bf16(c[mt][nt], al[mt], bh0, bh1);
                    mma_bf16(c[mt][nt], ah[mt], bl0, bl1);
                    mma_bf16(c[mt][nt], ah[mt], bh0, bh1);
                }
            }
        }
    }

    // ---- epilogue ----
#pragma unroll
    for (int mt = 0; mt < 4; mt++) {
#pragma unroll
        for (int nt = 0; nt < 4; nt++) {
            int n = n0 + wn * 32 + nt * 8 + t * 2;
            float2 bi = *(const float2*)(bias + n);
#pragma unroll
            for (int half = 0; half < 2; half++) {
                int m = m0 + wm * 64 + mt * 16 + g + half * 8;
                float2 val = make_float2(c[mt][nt][half * 2]     + bi.x,
                                         c[mt][nt][half * 2 + 1] + bi.y);
                if (head_layout) {
                    int bb = m >> 11;
                    int s  = m & (SEQ - 1);
                    int hh = n >> 6;
                    int d  = n & (DK - 1);
                    *(float2*)&Y[(((size_t)(bb * NH + hh) * SEQ) + s) * DK + d] = val;
                } else {
                    *(float2*)&Y[(size_t)m * D_MODEL + n] = val;
                }
            }
        }
    }
}

// ---------------------------------------------------------------------------
// Flash attention: mma.sync m16n8k16 bf16 3-term split, ldmatrix everywhere.
// CTA 128 thr / 4 warps; BQ=64 (warp w owns q rows w*16..+15); key tiles 64.
// K and V staged row-major [key][d] hi/lo; K frags via ldmatrix, V via
// ldmatrix.trans. Mask staged as 64-bit row bitmasks.
// ---------------------------------------------------------------------------
#define BKT  64
#define KST  72    // u16 row stride; 144B rows -> conflict-free LDSM

__global__ __launch_bounds__(128)
void attn_kernel(const int* __restrict__ mask)
{
    __shared__ uint16_t Ksm[2 * BKT * KST];   // [hi | lo]
    __shared__ uint16_t Vsm[2 * BKT * KST];
    __shared__ unsigned Mb[BKT * 2];          // per-row 64-bit mask

    const int tid  = threadIdx.x;
    const int w    = tid >> 5;
    const int lane = tid & 31;
    const int g    = lane >> 2;
    const int t    = lane & 3;
    const int b    = blockIdx.z;
    const int h    = blockIdx.y;
    const int qbase = blockIdx.x * 64;
    const size_t bh = ((size_t)b * NH + h) * SEQ;

    // ---- Q fragments (bf16 hi/lo) once ----
    unsigned ah[4][4], al[4][4];
    {
        const float* q0p = g_Qh + (bh + qbase + w * 16 + g) * DK;
        const float* q1p = q0p + 8 * DK;
#pragma unroll
        for (int kc = 0; kc < 4; kc++) {
            int d = kc * 16 + t * 2;
            split2(q0p[d],     q0p[d + 1], ah[kc][0], al[kc][0]);
            split2(q1p[d],     q1p[d + 1], ah[kc][1], al[kc][1]);
            split2(q0p[d + 8], q0p[d + 9], ah[kc][2], al[kc][2]);
            split2(q1p[d + 8], q1p[d + 9], ah[kc][3], al[kc][3]);
        }
    }

    float o[8][4];
#pragma unroll
    for (int nt = 0; nt < 8; nt++)
#pragma unroll
        for (int i = 0; i < 4; i++) o[nt][i] = 0.f;
    float mrow0 = -1e30f, mrow1 = -1e30f, lsum0 = 0.f, lsum1 = 0.f;

    const int r  = tid >> 1;
    const int hf = tid & 1;

    // per-lane LDSM bases (u16 units)
    const unsigned k_lane = (lane & 7) * KST + ((lane >> 3) & 1) * 8
                          + (lane >> 4) * (BKT * KST);
    const unsigned v_lane = ((lane & 7) + ((lane >> 3) & 1) * 8) * KST
                          + (lane >> 4) * (BKT * KST);
    const unsigned k_ad = (unsigned)__cvta_generic_to_shared(Ksm) + 2 * k_lane;
    const unsigned v_ad = (unsigned)__cvta_generic_to_shared(Vsm) + 2 * v_lane;

    for (int k0 = 0; k0 < SEQ; k0 += BKT) {
        __syncthreads();

        // ---- stage K/V hi/lo (row-major) + mask bitmask ----
        {
            const float* kp = g_Kh + (bh + k0 + r) * DK + hf * 32;
            const float* vp = g_Vh + (bh + k0 + r) * DK + hf * 32;
            const int*   mp = mask + (size_t)(qbase + r) * SEQ + k0 + hf * 32;
            unsigned mbits = 0;
#pragma unroll
            for (int j = 0; j < 8; j++) {
                int d = hf * 32 + 4 * j;
                float4 kv = *(const float4*)(kp + 4 * j);
                unsigned h01, l01, h23, l23;
                split2(kv.x, kv.y, h01, l01);
                split2(kv.z, kv.w, h23, l23);
                *(uint2*)&Ksm[r * KST + d]             = make_uint2(h01, h23);
                *(uint2*)&Ksm[BKT * KST + r * KST + d] = make_uint2(l01, l23);

                float4 vv = *(const float4*)(vp + 4 * j);
                split2(vv.x, vv.y, h01, l01);
                split2(vv.z, vv.w, h23, l23);
                *(uint2*)&Vsm[r * KST + d]             = make_uint2(h01, h23);
                *(uint2*)&Vsm[BKT * KST + r * KST + d] = make_uint2(l01, l23);

                int4 mv = *(const int4*)(mp + 4 * j);
                mbits |= (unsigned)(mv.x != 0) << (4 * j);
                mbits |= (unsigned)(mv.y != 0) << (4 * j + 1);
                mbits |= (unsigned)(mv.z != 0) << (4 * j + 2);
                mbits |= (unsigned)(mv.w != 0) << (4 * j + 3);
            }
            Mb[r * 2 + hf] = mbits;
        }
        __syncthreads();

        // ---- S = Q @ K^T (3-term) ----
        float s[8][4];
#pragma unroll
        for (int nt = 0; nt < 8; nt++) {
            float c[4] = {0.f, 0.f, 0.f, 0.f};
#pragma unroll
            for (int kc = 0; kc < 4; kc++) {
                unsigned bh0, bh1, bl0, bl1;
                ldsm_x4(bh0, bh1, bl0, bl1,
                        k_ad + 2 * (nt * 8 * KST + kc * 16));
                mma_bf16(c, al[kc], bh0, bh1);
                mma_bf16(c, ah[kc], bl0, bl1);
                mma_bf16(c, ah[kc], bh0, bh1);
            }
            s[nt][0] = c[0]; s[nt][1] = c[1]; s[nt][2] = c[2]; s[nt][3] = c[3];
        }

        // ---- mask (bitmask) + scale + online softmax ----
        {
            int row0 = w * 16 + g;
            unsigned long long M0 = (unsigned long long)Mb[row0 * 2]
                                  | ((unsigned long long)Mb[row0 * 2 + 1] << 32);
            unsigned long long M1 = (unsigned long long)Mb[(row0 + 8) * 2]
                                  | ((unsigned long long)Mb[(row0 + 8) * 2 + 1] << 32);
            float rmax0 = -1e30f, rmax1 = -1e30f;
#pragma unroll
            for (int nt = 0; nt < 8; nt++) {
                unsigned sh = nt * 8 + t * 2;
                unsigned b0 = (unsigned)(M0 >> sh);
                unsigned b1 = (unsigned)(M1 >> sh);
                s[nt][0] = (b0 & 1u) ? s[nt][0] * 0.125f : -1e9f;
                s[nt][1] = (b0 & 2u) ? s[nt][1] * 0.125f : -1e9f;
                s[nt][2] = (b1 & 1u) ? s[nt][2] * 0.125f : -1e9f;
                s[nt][3] = (b1 & 2u) ? s[nt][3] * 0.125f : -1e9f;
                rmax0 = fmaxf(rmax0, fmaxf(s[nt][0], s[nt][1]));
                rmax1 = fmaxf(rmax1, fmaxf(s[nt][2], s[nt][3]));
            }
            rmax0 = fmaxf(rmax0, __shfl_xor_sync(0xffffffffu, rmax0, 1));
            rmax0 = fmaxf(rmax0, __shfl_xor_sync(0xffffffffu, rmax0, 2));
            rmax1 = fmaxf(rmax1, __shfl_xor_sync(0xffffffffu, rmax1, 1));
            rmax1 = fmaxf(rmax1, __shfl_xor_sync(0xffffffffu, rmax1, 2));

            float mnew0 = fmaxf(mrow0, rmax0);
            float mnew1 = fmaxf(mrow1, rmax1);
            float corr0 = __expf(mrow0 - mnew0);
            float corr1 = __expf(mrow1 - mnew1);
            mrow0 = mnew0; mrow1 = mnew1;

            float sum0 = 0.f, sum1 = 0.f;
#pragma unroll
            for (int nt = 0; nt < 8; nt++) {
                s[nt][0] = __expf(s[nt][0] - mnew0);
                s[nt][1] = __expf(s[nt][1] - mnew0);
                s[nt][2] = __expf(s[nt][2] - mnew1);
                s[nt][3] = __expf(s[nt][3] - mnew1);
                sum0 += s[nt][0] + s[nt][1];
                sum1 += s[nt][2] + s[nt][3];
            }
            sum0 += __shfl_xor_sync(0xffffffffu, sum0, 1);
            sum0 += __shfl_xor_sync(0xffffffffu, sum0, 2);
            sum1 += __shfl_xor_sync(0xffffffffu, sum1, 1);
            sum1 += __shfl_xor_sync(0xffffffffu, sum1, 2);
            lsum0 = lsum0 * corr0 + sum0;
            lsum1 = lsum1 * corr1 + sum1;

#pragma unroll
            for (int nt = 0; nt < 8; nt++) {
                o[nt][0] *= corr0; o[nt][1] *= corr0;
                o[nt][2] *= corr1; o[nt][3] *= corr1;
            }
        }

        // ---- O += P @ V  (P frag = S C-frag layout; V via ldmatrix.trans) ----
#pragma unroll
        for (int kc = 0; kc < 4; kc++) {
            unsigned ph[4], pl[4];
            split2(s[2 * kc][0],     s[2 * kc][1],     ph[0], pl[0]);
            split2(s[2 * kc][2],     s[2 * kc][3],     ph[1], pl[1]);
            split2(s[2 * kc + 1][0], s[2 * kc + 1][1], ph[2], pl[2]);
            split2(s[2 * kc + 1][2], s[2 * kc + 1][3], ph[3], pl[3]);
#pragma unroll
            for (int nt = 0; nt < 8; nt++) {
                unsigned vh0, vh1, vl0, vl1;
                ldsm_x4_t(vh0, vh1, vl0, vl1,
                          v_ad + 2 * (kc * 16 * KST + nt * 8));
                mma_bf16(o[nt], pl, vh0, vh1);
                mma_bf16(o[nt], ph, vl0, vl1);
                mma_bf16(o[nt], ph, vh0, vh1);
            }
        }
    }

    // ---- epilogue: normalize, write concat layout [B, S, H*DK] ----
    float inv0 = 1.0f / lsum0;
    float inv1 = 1.0f / lsum1;
    int q0 = qbase + w * 16 + g;
    float* op0 = g_O + ((size_t)b * SEQ + q0) * D_MODEL + h * DK;
    float* op1 = op0 + 8 * (size_t)D_MODEL;
#pragma unroll
    for (int nt = 0; nt < 8; nt++) {
        *(float2*)(op0 + nt * 8 + t * 2) = make_float2(o[nt][0] * inv0, o[nt][1] * inv0);
        *(float2*)(op1 + nt * 8 + t * 2) = make_float2(o[nt][2] * inv1, o[nt][3] * inv1);
    }
}

// ---------------------------------------------------------------------------

extern "C" void kernel_launch(void* const* d_in, const int* in_sizes, int n_in,
                              void* d_out, int out_size)
{
    (void)in_sizes; (void)n_in; (void)out_size;
    const float* q    = (const float*)d_in[0];
    const float* k    = (const float*)d_in[1];
    const float* v    = (const float*)d_in[2];
    const int*   mask = (const int*)  d_in[3];
    const float* Wq   = (const float*)d_in[4];
    const float* bq   = (const float*)d_in[5];
    const float* Wk   = (const float*)d_in[6];
    const float* bk   = (const float*)d_in[7];
    const float* Wv   = (const float*)d_in[8];
    const float* bv   = (const float*)d_in[9];
    const float* Wo   = (const float*)d_in[10];
    const float* bo   = (const float*)d_in[11];
    float* out = (float*)d_out;

    float *Qh, *Kh, *Vh, *O;
    cudaGetSymbolAddress((void**)&Qh, g_Qh);
    cudaGetSymbolAddress((void**)&Kh, g_Kh);
    cudaGetSymbolAddress((void**)&Vh, g_Vh);
    cudaGetSymbolAddress((void**)&O,  g_O);

    dim3 proj_grid(D_MODEL / PBN, MTOT / PBM);   // (8, 64)
    proj_kernel<<<proj_grid, 128>>>(q, Wq, bq, Qh, 1);
    proj_kernel<<<proj_grid, 128>>>(k, Wk, bk, Kh, 1);
    proj_kernel<<<proj_grid, 128>>>(v, Wv, bv, Vh, 1);

    dim3 attn_grid(SEQ / 64, NH, BATCH);         // (32, 8, 4)
    attn_kernel<<<attn_grid, 128>>>(mask);

    proj_kernel<<<proj_grid, 128>>>(O, Wo, bo, out, 0);
}

// round 9
// speedup vs baseline: 3.8218x; 1.3821x over previous
#include <cuda_runtime.h>
#include <cuda_bf16.h>
#include <math.h>
#include <stdint.h>

#define D_MODEL 512
#define NH      8
#define DK      64
#define BATCH   4
#define SEQ     2048
#define MTOT    (BATCH * SEQ)   // 8192
#define NWORDS  (SEQ / 32)      // 64 mask words per row

// Scratch (allocation-free rule: __device__ globals)
__device__ float g_Qh[(size_t)BATCH * NH * SEQ * DK];
__device__ float g_O [(size_t)MTOT * D_MODEL];
__device__ __align__(16) uint16_t g_Khi[(size_t)BATCH * NH * SEQ * DK];
__device__ __align__(16) uint16_t g_Klo[(size_t)BATCH * NH * SEQ * DK];
__device__ __align__(16) uint16_t g_Vhi[(size_t)BATCH * NH * SEQ * DK];
__device__ __align__(16) uint16_t g_Vlo[(size_t)BATCH * NH * SEQ * DK];
__device__ __align__(16) unsigned g_Mb[(size_t)SEQ * NWORDS];

// ---------------------------------------------------------------------------
// bf16 helpers: pack2(e0,e1): e0 -> low half, e1 -> high half
// ---------------------------------------------------------------------------
__device__ __forceinline__ unsigned pack2(float e0, float e1) {
    unsigned r;
    asm("cvt.rn.bf16x2.f32 %0, %1, %2;" : "=r"(r) : "f"(e1), "f"(e0));
    return r;
}
__device__ __forceinline__ void split2(float x0, float x1,
                                       unsigned& hi, unsigned& lo) {
    hi = pack2(x0, x1);
    float h0 = __uint_as_float(hi << 16);
    float h1 = __uint_as_float(hi & 0xffff0000u);
    lo = pack2(x0 - h0, x1 - h1);
}

// m16n8k16 bf16 MMA, D += A*B
__device__ __forceinline__ void mma_bf16(float c[4], const unsigned a[4],
                                         unsigned b0, unsigned b1) {
    asm("mma.sync.aligned.m16n8k16.row.col.f32.bf16.bf16.f32 "
        "{%0,%1,%2,%3}, {%4,%5,%6,%7}, {%8,%9}, {%0,%1,%2,%3};"
        : "+f"(c[0]), "+f"(c[1]), "+f"(c[2]), "+f"(c[3])
        : "r"(a[0]), "r"(a[1]), "r"(a[2]), "r"(a[3]), "r"(b0), "r"(b1));
}

__device__ __forceinline__ void ldsm_x4(unsigned& r0, unsigned& r1,
                                        unsigned& r2, unsigned& r3,
                                        unsigned addr) {
    asm volatile("ldmatrix.sync.aligned.m8n8.x4.shared.b16 {%0,%1,%2,%3}, [%4];"
                 : "=r"(r0), "=r"(r1), "=r"(r2), "=r"(r3) : "r"(addr));
}
__device__ __forceinline__ void ldsm_x4_t(unsigned& r0, unsigned& r1,
                                          unsigned& r2, unsigned& r3,
                                          unsigned addr) {
    asm volatile("ldmatrix.sync.aligned.m8n8.x4.trans.shared.b16 {%0,%1,%2,%3}, [%4];"
                 : "=r"(r0), "=r"(r1), "=r"(r2), "=r"(r3) : "r"(addr));
}

// cp.async helpers
__device__ __forceinline__ void cp16(unsigned saddr, const void* g) {
    asm volatile("cp.async.cg.shared.global [%0], [%1], 16;"
                 :: "r"(saddr), "l"(g));
}
__device__ __forceinline__ void cp8(unsigned saddr, const void* g) {
    asm volatile("cp.async.ca.shared.global [%0], [%1], 8;"
                 :: "r"(saddr), "l"(g));
}
__device__ __forceinline__ void cp_commit() {
    asm volatile("cp.async.commit_group;");
}
template<int N> __device__ __forceinline__ void cp_wait() {
    asm volatile("cp.async.wait_group %0;" :: "n"(N));
}

// ---------------------------------------------------------------------------
// Mask bitmask precompute: g_Mb[q*NWORDS + w] bit j = (mask[q][32w+j] != 0)
// ---------------------------------------------------------------------------
__global__ __launch_bounds__(256)
void mask_bits_kernel(const int* __restrict__ mask)
{
    int w = blockIdx.x * 256 + threadIdx.x;          // 0 .. SEQ*NWORDS-1
    const int* mp = mask + (size_t)w * 32;
    unsigned bits = 0;
#pragma unroll
    for (int j = 0; j < 8; j++) {
        int4 m = *(const int4*)(mp + 4 * j);
        bits |= (unsigned)(m.x != 0) << (4 * j);
        bits |= (unsigned)(m.y != 0) << (4 * j + 1);
        bits |= (unsigned)(m.z != 0) << (4 * j + 2);
        bits |= (unsigned)(m.w != 0) << (4 * j + 3);
    }
    g_Mb[w] = bits;
}

// ---------------------------------------------------------------------------
// Projection GEMM on tensor cores: Y = X @ W^T + b, 3-term bf16 split.
// mode 0: f32 [M,512]; mode 1: f32 head layout; mode 2: bf16 hi/lo head layout
// ---------------------------------------------------------------------------
#define PBM  128
#define PBN  64
#define PBK  32
#define PKST 40

__global__ __launch_bounds__(128)
void proj_kernel(const float* __restrict__ A,
                 const float* __restrict__ W,
                 const float* __restrict__ bias,
                 float* __restrict__ Yf,
                 uint16_t* __restrict__ Yhi,
                 uint16_t* __restrict__ Ylo,
                 int mode)
{
    __shared__ uint16_t Asm[2 * PBM * PKST];   // [hi | lo]
    __shared__ uint16_t Bsm[2 * PBN * PKST];

    const int tid  = threadIdx.x;
    const int lane = tid & 31;
    const int w    = tid >> 5;
    const int wm   = w & 1;
    const int wn   = w >> 1;
    const int g    = lane >> 2;
    const int t    = lane & 3;
    const int m0   = blockIdx.y * PBM;
    const int n0   = blockIdx.x * PBN;

    float c[4][4][4];
#pragma unroll
    for (int i = 0; i < 4; i++)
#pragma unroll
        for (int j = 0; j < 4; j++)
#pragma unroll
            for (int q = 0; q < 4; q++) c[i][j][q] = 0.f;

    const unsigned a_lane = (wm * 64 + ((lane >> 3) & 1) * 8 + (lane & 7)) * PKST
                          + (lane >> 4) * 8;
    const unsigned b_lane = (wn * 32 + (lane & 7)) * PKST
                          + ((lane >> 3) & 1) * 8
                          + (lane >> 4) * (PBN * PKST);
    const unsigned a_hi = (unsigned)__cvta_generic_to_shared(Asm) + 2 * a_lane;
    const unsigned a_lo = a_hi + 2 * (PBM * PKST);
    const unsigned b_ad = (unsigned)__cvta_generic_to_shared(Bsm) + 2 * b_lane;

    for (int k0 = 0; k0 < D_MODEL; k0 += PBK) {
        __syncthreads();
#pragma unroll
        for (int l = 0; l < 8; l++) {
            int v = l * 128 + tid;
            int row = v >> 3;
            int c4  = v & 7;
            float4 a = *(const float4*)(A + (size_t)(m0 + row) * D_MODEL + k0 + c4 * 4);
            unsigned h01, l01, h23, l23;
            split2(a.x, a.y, h01, l01);
            split2(a.z, a.w, h23, l23);
            *(uint2*)&Asm[row * PKST + c4 * 4]              = make_uint2(h01, h23);
            *(uint2*)&Asm[PBM * PKST + row * PKST + c4 * 4] = make_uint2(l01, l23);
        }
#pragma unroll
        for (int l = 0; l < 4; l++) {
            int v = l * 128 + tid;
            int row = v >> 3;
            int c4  = v & 7;
            float4 b = *(const float4*)(W + (size_t)(n0 + row) * D_MODEL + k0 + c4 * 4);
            unsigned h01, l01, h23, l23;
            split2(b.x, b.y, h01, l01);
            split2(b.z, b.w, h23, l23);
            *(uint2*)&Bsm[row * PKST + c4 * 4]              = make_uint2(h01, h23);
            *(uint2*)&Bsm[PBN * PKST + row * PKST + c4 * 4] = make_uint2(l01, l23);
        }
        __syncthreads();

#pragma unroll
        for (int kk = 0; kk < 2; kk++) {
            unsigned ah[4][4], al[4][4];
#pragma unroll
            for (int mt = 0; mt < 4; mt++) {
                unsigned off = 2 * (mt * 16 * PKST + kk * 16);
                ldsm_x4(ah[mt][0], ah[mt][1], ah[mt][2], ah[mt][3], a_hi + off);
                ldsm_x4(al[mt][0], al[mt][1], al[mt][2], al[mt][3], a_lo + off);
            }
#pragma unroll
            for (int nt = 0; nt < 4; nt++) {
                unsigned bh0, bh1, bl0, bl1;
                ldsm_x4(bh0, bh1, bl0, bl1,
                        b_ad + 2 * (nt * 8 * PKST + kk * 16));
#pragma unroll
                for (int mt = 0; mt < 4; mt++) {
                    mma_bf16(c[mt][nt], al[mt], bh0, bh1);
                    mma_bf16(c[mt][nt], ah[mt], bl0, bl1);
                    mma_bf16(c[mt][nt], ah[mt], bh0, bh1);
                }
            }
        }
    }

    // ---- epilogue ----
#pragma unroll
    for (int mt = 0; mt < 4; mt++) {
#pragma unroll
        for (int nt = 0; nt < 4; nt++) {
            int n = n0 + wn * 32 + nt * 8 + t * 2;
            float2 bi = *(const float2*)(bias + n);
#pragma unroll
            for (int half = 0; half < 2; half++) {
                int m = m0 + wm * 64 + mt * 16 + g + half * 8;
                float2 val = make_float2(c[mt][nt][half * 2]     + bi.x,
                                         c[mt][nt][half * 2 + 1] + bi.y);
                if (mode == 0) {
                    *(float2*)&Yf[(size_t)m * D_MODEL + n] = val;
                } else {
                    int bb = m >> 11;
                    int s  = m & (SEQ - 1);
                    int hh = n >> 6;
                    int d  = n & (DK - 1);
                    size_t idx = (((size_t)(bb * NH + hh) * SEQ) + s) * DK + d;
                    if (mode == 1) {
                        *(float2*)&Yf[idx] = val;
                    } else {
                        unsigned hi, lo;
                        split2(val.x, val.y, hi, lo);
                        *(unsigned*)&Yhi[idx] = hi;
                        *(unsigned*)&Ylo[idx] = lo;
                    }
                }
            }
        }
    }
}

// ---------------------------------------------------------------------------
// Flash attention: bf16 mma.sync, pre-split K/V, cp.async double buffering.
// CTA 128 thr / 4 warps; BQ=64; key tiles 64. Dynamic smem:
//   stage s (s=0,1) at byte s*STG_BYTES: [Khi | Klo | Vhi | Vlo], each 64xKST u16
//   mask words at MS_OFF_BYTES: unsigned[2][128]
// ---------------------------------------------------------------------------
#define BKT   64
#define NT_T  (SEQ / BKT)          // 32 tiles
#define KST   72
#define MAT_U16   (64 * KST)       // 4608
#define MAT_BYTES (MAT_U16 * 2)    // 9216
#define STG_BYTES (4 * MAT_BYTES)  // 36864
#define MS_OFF_BYTES (2 * STG_BYTES)
#define ATTN_SMEM (MS_OFF_BYTES + 2 * 128 * 4)   // 74752

__device__ __forceinline__ void stage_tile(unsigned smem_u32, int st,
                                           size_t bh, int qbase, int tile,
                                           int tid)
{
    const int k0 = tile * BKT;
    const unsigned sb = smem_u32 + st * STG_BYTES;
#pragma unroll
    for (int l = 0; l < 4; l++) {
        int cc  = tid + l * 128;
        int row = cc >> 3;
        int col = cc & 7;
        size_t  go = (size_t)(bh + k0 + row) * DK + col * 8;
        unsigned so = 2 * (row * KST + col * 8);
        cp16(sb + so,                 g_Khi + go);
        cp16(sb + MAT_BYTES + so,     g_Klo + go);
        cp16(sb + 2 * MAT_BYTES + so, g_Vhi + go);
        cp16(sb + 3 * MAT_BYTES + so, g_Vlo + go);
    }
    if (tid < 64) {
        cp8(smem_u32 + MS_OFF_BYTES + st * 512 + tid * 8,
            g_Mb + (size_t)(qbase + tid) * NWORDS + tile * 2);
    }
    cp_commit();
}

__global__ __launch_bounds__(128)
void attn_kernel()
{
    extern __shared__ char dsm[];
    const unsigned smem_u32 = (unsigned)__cvta_generic_to_shared(dsm);
    const unsigned* Msp = (const unsigned*)(dsm + MS_OFF_BYTES);

    const int tid  = threadIdx.x;
    const int w    = tid >> 5;
    const int lane = tid & 31;
    const int g    = lane >> 2;
    const int t    = lane & 3;
    const int b    = blockIdx.z;
    const int h    = blockIdx.y;
    const int qbase = blockIdx.x * 64;
    const size_t bh = ((size_t)b * NH + h) * SEQ;

    // prefetch tile 0 first, then load Q (overlaps with cp.async)
    stage_tile(smem_u32, 0, bh, qbase, 0, tid);

    // ---- Q fragments (bf16 hi/lo) once ----
    unsigned ah[4][4], al[4][4];
    {
        const float* q0p = g_Qh + (bh + qbase + w * 16 + g) * DK;
        const float* q1p = q0p + 8 * DK;
#pragma unroll
        for (int kc = 0; kc < 4; kc++) {
            int d = kc * 16 + t * 2;
            split2(q0p[d],     q0p[d + 1], ah[kc][0], al[kc][0]);
            split2(q1p[d],     q1p[d + 1], ah[kc][1], al[kc][1]);
            split2(q0p[d + 8], q0p[d + 9], ah[kc][2], al[kc][2]);
            split2(q1p[d + 8], q1p[d + 9], ah[kc][3], al[kc][3]);
        }
    }

    float o[8][4];
#pragma unroll
    for (int nt = 0; nt < 8; nt++)
#pragma unroll
        for (int i = 0; i < 4; i++) o[nt][i] = 0.f;
    float mrow0 = -1e30f, mrow1 = -1e30f, lsum0 = 0.f, lsum1 = 0.f;

    // per-lane LDSM bases (byte addresses, stage 0)
    const unsigned k_lane = (lane & 7) * KST + ((lane >> 3) & 1) * 8
                          + (lane >> 4) * MAT_U16;
    const unsigned v_lane = ((lane & 7) + ((lane >> 3) & 1) * 8) * KST
                          + (lane >> 4) * MAT_U16;
    const unsigned k_ad = smem_u32 + 2 * k_lane;
    const unsigned v_ad = smem_u32 + 2 * MAT_BYTES + 2 * v_lane;

    for (int tile = 0; tile < NT_T; tile++) {
        const int st = tile & 1;
        __syncthreads();   // all warps done computing tile-1 (stage st^1)
        if (tile + 1 < NT_T) {
            stage_tile(smem_u32, st ^ 1, bh, qbase, tile + 1, tid);
            cp_wait<1>();
        } else {
            cp_wait<0>();
        }
        __syncthreads();   // stage st visible to all

        const unsigned kst_ad = k_ad + st * STG_BYTES;
        const unsigned vst_ad = v_ad + st * STG_BYTES;

        // ---- S = Q @ K^T (3-term) ----
        float s[8][4];
#pragma unroll
        for (int nt = 0; nt < 8; nt++) {
            float c[4] = {0.f, 0.f, 0.f, 0.f};
#pragma unroll
            for (int kc = 0; kc < 4; kc++) {
                unsigned bh0, bh1, bl0, bl1;
                ldsm_x4(bh0, bh1, bl0, bl1,
                        kst_ad + 2 * (nt * 8 * KST + kc * 16));
                mma_bf16(c, al[kc], bh0, bh1);
                mma_bf16(c, ah[kc], bl0, bl1);
                mma_bf16(c, ah[kc], bh0, bh1);
            }
            s[nt][0] = c[0]; s[nt][1] = c[1]; s[nt][2] = c[2]; s[nt][3] = c[3];
        }

        // ---- mask (bitmask) + scale + online softmax ----
        {
            int row0 = w * 16 + g;
            const unsigned* ms = Msp + st * 128;
            unsigned long long M0 = (unsigned long long)ms[row0 * 2]
                                  | ((unsigned long long)ms[row0 * 2 + 1] << 32);
            unsigned long long M1 = (unsigned long long)ms[(row0 + 8) * 2]
                                  | ((unsigned long long)ms[(row0 + 8) * 2 + 1] << 32);
            float rmax0 = -1e30f, rmax1 = -1e30f;
#pragma unroll
            for (int nt = 0; nt < 8; nt++) {
                unsigned sh = nt * 8 + t * 2;
                unsigned b0 = (unsigned)(M0 >> sh);
                unsigned b1 = (unsigned)(M1 >> sh);
                s[nt][0] = (b0 & 1u) ? s[nt][0] * 0.125f : -1e9f;
                s[nt][1] = (b0 & 2u) ? s[nt][1] * 0.125f : -1e9f;
                s[nt][2] = (b1 & 1u) ? s[nt][2] * 0.125f : -1e9f;
                s[nt][3] = (b1 & 2u) ? s[nt][3] * 0.125f : -1e9f;
                rmax0 = fmaxf(rmax0, fmaxf(s[nt][0], s[nt][1]));
                rmax1 = fmaxf(rmax1, fmaxf(s[nt][2], s[nt][3]));
            }
            rmax0 = fmaxf(rmax0, __shfl_xor_sync(0xffffffffu, rmax0, 1));
            rmax0 = fmaxf(rmax0, __shfl_xor_sync(0xffffffffu, rmax0, 2));
            rmax1 = fmaxf(rmax1, __shfl_xor_sync(0xffffffffu, rmax1, 1));
            rmax1 = fmaxf(rmax1, __shfl_xor_sync(0xffffffffu, rmax1, 2));

            float mnew0 = fmaxf(mrow0, rmax0);
            float mnew1 = fmaxf(mrow1, rmax1);
            float corr0 = __expf(mrow0 - mnew0);
            float corr1 = __expf(mrow1 - mnew1);
            mrow0 = mnew0; mrow1 = mnew1;

            float sum0 = 0.f, sum1 = 0.f;
#pragma unroll
            for (int nt = 0; nt < 8; nt++) {
                s[nt][0] = __expf(s[nt][0] - mnew0);
                s[nt][1] = __expf(s[nt][1] - mnew0);
                s[nt][2] = __expf(s[nt][2] - mnew1);
                s[nt][3] = __expf(s[nt][3] - mnew1);
                sum0 += s[nt][0] + s[nt][1];
                sum1 += s[nt][2] + s[nt][3];
            }
            sum0 += __shfl_xor_sync(0xffffffffu, sum0, 1);
            sum0 += __shfl_xor_sync(0xffffffffu, sum0, 2);
            sum1 += __shfl_xor_sync(0xffffffffu, sum1, 1);
            sum1 += __shfl_xor_sync(0xffffffffu, sum1, 2);
            lsum0 = lsum0 * corr0 + sum0;
            lsum1 = lsum1 * corr1 + sum1;

#pragma unroll
            for (int nt = 0; nt < 8; nt++) {
                o[nt][0] *= corr0; o[nt][1] *= corr0;
                o[nt][2] *= corr1; o[nt][3] *= corr1;
            }
        }

        // ---- O += P @ V ----
#pragma unroll
        for (int kc = 0; kc < 4; kc++) {
            unsigned ph[4], pl[4];
            split2(s[2 * kc][0],     s[2 * kc][1],     ph[0], pl[0]);
            split2(s[2 * kc][2],     s[2 * kc][3],     ph[1], pl[1]);
            split2(s[2 * kc + 1][0], s[2 * kc + 1][1], ph[2], pl[2]);
            split2(s[2 * kc + 1][2], s[2 * kc + 1][3], ph[3], pl[3]);
#pragma unroll
            for (int nt = 0; nt < 8; nt++) {
                unsigned vh0, vh1, vl0, vl1;
                ldsm_x4_t(vh0, vh1, vl0, vl1,
                          vst_ad + 2 * (kc * 16 * KST + nt * 8));
                mma_bf16(o[nt], pl, vh0, vh1);
                mma_bf16(o[nt], ph, vl0, vl1);
                mma_bf16(o[nt], ph, vh0, vh1);
            }
        }
    }

    // ---- epilogue ----
    float inv0 = 1.0f / lsum0;
    float inv1 = 1.0f / lsum1;
    int q0 = qbase + w * 16 + g;
    float* op0 = g_O + ((size_t)b * SEQ + q0) * D_MODEL + h * DK;
    float* op1 = op0 + 8 * (size_t)D_MODEL;
#pragma unroll
    for (int nt = 0; nt < 8; nt++) {
        *(float2*)(op0 + nt * 8 + t * 2) = make_float2(o[nt][0] * inv0, o[nt][1] * inv0);
        *(float2*)(op1 + nt * 8 + t * 2) = make_float2(o[nt][2] * inv1, o[nt][3] * inv1);
    }
}

// ---------------------------------------------------------------------------

extern "C" void kernel_launch(void* const* d_in, const int* in_sizes, int n_in,
                              void* d_out, int out_size)
{
    (void)in_sizes; (void)n_in; (void)out_size;
    const float* q    = (const float*)d_in[0];
    const float* k    = (const float*)d_in[1];
    const float* v    = (const float*)d_in[2];
    const int*   mask = (const int*)  d_in[3];
    const float* Wq   = (const float*)d_in[4];
    const float* bq   = (const float*)d_in[5];
    const float* Wk   = (const float*)d_in[6];
    const float* bk   = (const float*)d_in[7];
    const float* Wv   = (const float*)d_in[8];
    const float* bv   = (const float*)d_in[9];
    const float* Wo   = (const float*)d_in[10];
    const float* bo   = (const float*)d_in[11];
    float* out = (float*)d_out;

    float *Qh, *O;
    uint16_t *Khi, *Klo, *Vhi, *Vlo;
    cudaGetSymbolAddress((void**)&Qh,  g_Qh);
    cudaGetSymbolAddress((void**)&O,   g_O);
    cudaGetSymbolAddress((void**)&Khi, g_Khi);
    cudaGetSymbolAddress((void**)&Klo, g_Klo);
    cudaGetSymbolAddress((void**)&Vhi, g_Vhi);
    cudaGetSymbolAddress((void**)&Vlo, g_Vlo);

    cudaFuncSetAttribute(attn_kernel,
                         cudaFuncAttributeMaxDynamicSharedMemorySize,
                         ATTN_SMEM);

    mask_bits_kernel<<<SEQ * NWORDS / 256, 256>>>(mask);

    dim3 proj_grid(D_MODEL / PBN, MTOT / PBM);   // (8, 64)
    proj_kernel<<<proj_grid, 128>>>(q, Wq, bq, Qh,  nullptr, nullptr, 1);
    proj_kernel<<<proj_grid, 128>>>(k, Wk, bk, nullptr, Khi, Klo, 2);
    proj_kernel<<<proj_grid, 128>>>(v, Wv, bv, nullptr, Vhi, Vlo, 2);

    dim3 attn_grid(SEQ / 64, NH, BATCH);         // (32, 8, 4)
    attn_kernel<<<attn_grid, 128, ATTN_SMEM>>>();

    proj_kernel<<<proj_grid, 128>>>(O, Wo, bo, out, nullptr, nullptr, 0);
}

// round 12
// speedup vs baseline: 4.2429x; 1.1102x over previous
#include <cuda_runtime.h>
#include <cuda_bf16.h>
#include <math.h>
#include <stdint.h>

#define D_MODEL 512
#define NH      8
#define DK      64
#define BATCH   4
#define SEQ     2048
#define MTOT    (BATCH * SEQ)   // 8192
#define NWORDS  (SEQ / 32)      // 64 mask words per row
#define IN_SZ   ((size_t)MTOT * D_MODEL)     // 4194304
#define W_SZ    ((size_t)D_MODEL * D_MODEL)  // 262144

// Scratch (allocation-free rule: __device__ globals)
__device__ float g_Qh[IN_SZ];
__device__ __align__(16) uint16_t g_Inhi[3 * IN_SZ];
__device__ __align__(16) uint16_t g_Inlo[3 * IN_SZ];
__device__ __align__(16) uint16_t g_Whi[4 * W_SZ];
__device__ __align__(16) uint16_t g_Wlo[4 * W_SZ];
__device__ __align__(16) uint16_t g_Khi[IN_SZ];
__device__ __align__(16) uint16_t g_Klo[IN_SZ];
__device__ __align__(16) uint16_t g_Vhi[IN_SZ];
__device__ __align__(16) uint16_t g_Vlo[IN_SZ];
__device__ __align__(16) uint16_t g_Ohi[IN_SZ];
__device__ __align__(16) uint16_t g_Olo[IN_SZ];
__device__ __align__(16) unsigned g_Mb[(size_t)SEQ * NWORDS];

// ---------------------------------------------------------------------------
// bf16 helpers: pack2(e0,e1): e0 -> low half, e1 -> high half
// ---------------------------------------------------------------------------
__device__ __forceinline__ unsigned pack2(float e0, float e1) {
    unsigned r;
    asm("cvt.rn.bf16x2.f32 %0, %1, %2;" : "=r"(r) : "f"(e1), "f"(e0));
    return r;
}
__device__ __forceinline__ void split2(float x0, float x1,
                                       unsigned& hi, unsigned& lo) {
    hi = pack2(x0, x1);
    float h0 = __uint_as_float(hi << 16);
    float h1 = __uint_as_float(hi & 0xffff0000u);
    lo = pack2(x0 - h0, x1 - h1);
}

// m16n8k16 bf16 MMA, D += A*B
__device__ __forceinline__ void mma_bf16(float c[4], const unsigned a[4],
                                         unsigned b0, unsigned b1) {
    asm("mma.sync.aligned.m16n8k16.row.col.f32.bf16.bf16.f32 "
        "{%0,%1,%2,%3}, {%4,%5,%6,%7}, {%8,%9}, {%0,%1,%2,%3};"
        : "+f"(c[0]), "+f"(c[1]), "+f"(c[2]), "+f"(c[3])
        : "r"(a[0]), "r"(a[1]), "r"(a[2]), "r"(a[3]), "r"(b0), "r"(b1));
}

__device__ __forceinline__ void ldsm_x4(unsigned& r0, unsigned& r1,
                                        unsigned& r2, unsigned& r3,
                                        unsigned addr) {
    asm volatile("ldmatrix.sync.aligned.m8n8.x4.shared.b16 {%0,%1,%2,%3}, [%4];"
                 : "=r"(r0), "=r"(r1), "=r"(r2), "=r"(r3) : "r"(addr));
}
__device__ __forceinline__ void ldsm_x4_t(unsigned& r0, unsigned& r1,
                                          unsigned& r2, unsigned& r3,
                                          unsigned addr) {
    asm volatile("ldmatrix.sync.aligned.m8n8.x4.trans.shared.b16 {%0,%1,%2,%3}, [%4];"
                 : "=r"(r0), "=r"(r1), "=r"(r2), "=r"(r3) : "r"(addr));
}

// cp.async helpers
__device__ __forceinline__ void cp16(unsigned saddr, const void* g) {
    asm volatile("cp.async.cg.shared.global [%0], [%1], 16;"
                 :: "r"(saddr), "l"(g));
}
__device__ __forceinline__ void cp8(unsigned saddr, const void* g) {
    asm volatile("cp.async.ca.shared.global [%0], [%1], 8;"
                 :: "r"(saddr), "l"(g));
}
__device__ __forceinline__ void cp_commit() {
    asm volatile("cp.async.commit_group;");
}
template<int N> __device__ __forceinline__ void cp_wait() {
    asm volatile("cp.async.wait_group %0;" :: "n"(N));
}

// ---------------------------------------------------------------------------
// Prep kernels
// ---------------------------------------------------------------------------
__global__ __launch_bounds__(256)
void mask_bits_kernel(const int* __restrict__ mask)
{
    int w = blockIdx.x * 256 + threadIdx.x;
    const int* mp = mask + (size_t)w * 32;
    unsigned bits = 0;
#pragma unroll
    for (int j = 0; j < 8; j++) {
        int4 m = *(const int4*)(mp + 4 * j);
        bits |= (unsigned)(m.x != 0) << (4 * j);
        bits |= (unsigned)(m.y != 0) << (4 * j + 1);
        bits |= (unsigned)(m.z != 0) << (4 * j + 2);
        bits |= (unsigned)(m.w != 0) << (4 * j + 3);
    }
    g_Mb[w] = bits;
}

__global__ __launch_bounds__(256)
void split_in_kernel(const float* __restrict__ q,
                     const float* __restrict__ k,
                     const float* __restrict__ v)
{
    int which = blockIdx.y;
    const float* src = (which == 0) ? q : (which == 1) ? k : v;
    size_t i = ((size_t)blockIdx.x * 256 + threadIdx.x) * 4;
    float4 x = *(const float4*)(src + i);
    unsigned h01, l01, h23, l23;
    split2(x.x, x.y, h01, l01);
    split2(x.z, x.w, h23, l23);
    size_t o = (size_t)which * IN_SZ + i;
    *(uint2*)&g_Inhi[o] = make_uint2(h01, h23);
    *(uint2*)&g_Inlo[o] = make_uint2(l01, l23);
}

__global__ __launch_bounds__(256)
void split_w_kernel(const float* __restrict__ w0,
                    const float* __restrict__ w1,
                    const float* __restrict__ w2,
                    const float* __restrict__ w3)
{
    int which = blockIdx.y;
    const float* src = (which == 0) ? w0 : (which == 1) ? w1
                     : (which == 2) ? w2 : w3;
    size_t i = ((size_t)blockIdx.x * 256 + threadIdx.x) * 4;
    float4 x = *(const float4*)(src + i);
    unsigned h01, l01, h23, l23;
    split2(x.x, x.y, h01, l01);
    split2(x.z, x.w, h23, l23);
    size_t o = (size_t)which * W_SZ + i;
    *(uint2*)&g_Whi[o] = make_uint2(h01, h23);
    *(uint2*)&g_Wlo[o] = make_uint2(l01, l23);
}

// ---------------------------------------------------------------------------
// Projection GEMM: all operands pre-split bf16 hi/lo, cp.async double buffer.
// Tile 128(M) x 64(N) x 32(K-step). 128 threads / 4 warps.
// mode 0: f32 [M,512]; mode 1: f32 head layout; mode 2: bf16 hi/lo head layout
// Stage layout (u16 idx): Ahi[0] Alo[PBM*PKST] Whi[2*PBM*PKST] Wlo[+PBN*PKST]
// ---------------------------------------------------------------------------
#define PBM  128
#define PBN  64
#define PBK  32
#define PKST 40
#define P_STG_U16   (2 * PBM * PKST + 2 * PBN * PKST)   // 15360
#define P_STG_BYTES (P_STG_U16 * 2)                      // 30720
#define PROJ_SMEM   (2 * P_STG_BYTES)                    // 61440
#define NKI  (D_MODEL / PBK)                             // 16

__device__ __forceinline__ void proj_stage(unsigned sb,
        const uint16_t* __restrict__ Ahi, const uint16_t* __restrict__ Alo,
        const uint16_t* __restrict__ Whi, const uint16_t* __restrict__ Wlo,
        int m0, int n0, int k0, int tid)
{
#pragma unroll
    for (int l = 0; l < 4; l++) {
        int v   = l * 128 + tid;
        int row = v >> 2, cb = v & 3;
        size_t   go = (size_t)(m0 + row) * D_MODEL + k0 + cb * 8;
        unsigned so = 2u * (row * PKST + cb * 8);
        cp16(sb + so,                     Ahi + go);
        cp16(sb + 2u * PBM * PKST + so,   Alo + go);
    }
#pragma unroll
    for (int l = 0; l < 2; l++) {
        int v   = l * 128 + tid;
        int row = v >> 2, cb = v & 3;
        size_t   go = (size_t)(n0 + row) * D_MODEL + k0 + cb * 8;
        unsigned so = 2u * (row * PKST + cb * 8);
        cp16(sb + 4u * PBM * PKST + so,                     Whi + go);
        cp16(sb + 4u * PBM * PKST + 2u * PBN * PKST + so,   Wlo + go);
    }
    cp_commit();
}

__global__ __launch_bounds__(128)
void proj_kernel(const uint16_t* __restrict__ Ahi,
                 const uint16_t* __restrict__ Alo,
                 const uint16_t* __restrict__ Whi,
                 const uint16_t* __restrict__ Wlo,
                 const float* __restrict__ bias,
                 float* __restrict__ Yf,
                 uint16_t* __restrict__ Yhi,
                 uint16_t* __restrict__ Ylo,
                 int mode)
{
    extern __shared__ char psm[];
    const unsigned sbase = (unsigned)__cvta_generic_to_shared(psm);

    const int tid  = threadIdx.x;
    const int lane = tid & 31;
    const int w    = tid >> 5;
    const int wm   = w & 1;
    const int wn   = w >> 1;
    const int g    = lane >> 2;
    const int t    = lane & 3;
    const int m0   = blockIdx.y * PBM;
    const int n0   = blockIdx.x * PBN;

    float c[4][4][4];
#pragma unroll
    for (int i = 0; i < 4; i++)
#pragma unroll
        for (int j = 0; j < 4; j++)
#pragma unroll
            for (int q = 0; q < 4; q++) c[i][j][q] = 0.f;

    // per-lane LDSM byte offsets within a stage
    const unsigned a_lane = (wm * 64 + ((lane >> 3) & 1) * 8 + (lane & 7)) * PKST
                          + (lane >> 4) * 8;
    const unsigned b_lane = (wn * 32 + (lane & 7)) * PKST
                          + ((lane >> 3) & 1) * 8
                          + (lane >> 4) * (PBN * PKST);
    const unsigned a_hi_off = 2 * a_lane;
    const unsigned a_lo_off = a_hi_off + 2 * (PBM * PKST);
    const unsigned b_off    = 4 * PBM * PKST + 2 * b_lane;

    proj_stage(sbase, Ahi, Alo, Whi, Wlo, m0, n0, 0, tid);

    for (int ki = 0; ki < NKI; ki++) {
        const int st = ki & 1;
        __syncthreads();   // all warps done computing prev stage (st^1)
        if (ki + 1 < NKI) {
            proj_stage(sbase + (st ^ 1) * P_STG_BYTES,
                       Ahi, Alo, Whi, Wlo, m0, n0, (ki + 1) * PBK, tid);
            cp_wait<1>();
        } else {
            cp_wait<0>();
        }
        __syncthreads();   // stage st visible

        const unsigned sb = sbase + st * P_STG_BYTES;
#pragma unroll
        for (int kk = 0; kk < 2; kk++) {
            unsigned ah[4][4], al[4][4];
#pragma unroll
            for (int mt = 0; mt < 4; mt++) {
                unsigned off = 2 * (mt * 16 * PKST + kk * 16);
                ldsm_x4(ah[mt][0], ah[mt][1], ah[mt][2], ah[mt][3],
                        sb + a_hi_off + off);
                ldsm_x4(al[mt][0], al[mt][1], al[mt][2], al[mt][3],
                        sb + a_lo_off + off);
            }
#pragma unroll
            for (int nt = 0; nt < 4; nt++) {
                unsigned bh0, bh1, bl0, bl1;
                ldsm_x4(bh0, bh1, bl0, bl1,
                        sb + b_off + 2 * (nt * 8 * PKST + kk * 16));
#pragma unroll
                for (int mt = 0; mt < 4; mt++) {
                    mma_bf16(c[mt][nt], al[mt], bh0, bh1);
                    mma_bf16(c[mt][nt], ah[mt], bl0, bl1);
                    mma_bf16(c[mt][nt], ah[mt], bh0, bh1);
                }
            }
        }
    }

    // ---- epilogue ----
#pragma unroll
    for (int mt = 0; mt < 4; mt++) {
#pragma unroll
        for (int nt = 0; nt < 4; nt++) {
            int n = n0 + wn * 32 + nt * 8 + t * 2;
            float2 bi = *(const float2*)(bias + n);
#pragma unroll
            for (int half = 0; half < 2; half++) {
                int m = m0 + wm * 64 + mt * 16 + g + half * 8;
                float2 val = make_float2(c[mt][nt][half * 2]     + bi.x,
                                         c[mt][nt][half * 2 + 1] + bi.y);
                if (mode == 0) {
                    *(float2*)&Yf[(size_t)m * D_MODEL + n] = val;
                } else {
                    int bb = m >> 11;
                    int s  = m & (SEQ - 1);
                    int hh = n >> 6;
                    int d  = n & (DK - 1);
                    size_t idx = (((size_t)(bb * NH + hh) * SEQ) + s) * DK + d;
                    if (mode == 1) {
                        *(float2*)&Yf[idx] = val;
                    } else {
                        unsigned hi, lo;
                        split2(val.x, val.y, hi, lo);
                        *(unsigned*)&Yhi[idx] = hi;
                        *(unsigned*)&Ylo[idx] = lo;
                    }
                }
            }
        }
    }
}

// ---------------------------------------------------------------------------
// Flash attention (R9 structure; bf16 hi/lo output).
// ---------------------------------------------------------------------------
#define BKT   64
#define NT_T  (SEQ / BKT)          // 32 tiles
#define KST   72
#define MAT_U16   (64 * KST)       // 4608
#define MAT_BYTES (MAT_U16 * 2)    // 9216
#define STG_BYTES (4 * MAT_BYTES)  // 36864
#define MS_OFF_BYTES (2 * STG_BYTES)
#define ATTN_SMEM (MS_OFF_BYTES + 2 * 128 * 4)   // 74752

__device__ __forceinline__ void stage_tile(unsigned smem_u32, int st,
                                           size_t bh, int qbase, int tile,
                                           int tid)
{
    const int k0 = tile * BKT;
    const unsigned sb = smem_u32 + st * STG_BYTES;
#pragma unroll
    for (int l = 0; l < 4; l++) {
        int cc  = tid + l * 128;
        int row = cc >> 3;
        int col = cc & 7;
        size_t  go = (size_t)(bh + k0 + row) * DK + col * 8;
        unsigned so = 2 * (row * KST + col * 8);
        cp16(sb + so,                 g_Khi + go);
        cp16(sb + MAT_BYTES + so,     g_Klo + go);
        cp16(sb + 2 * MAT_BYTES + so, g_Vhi + go);
        cp16(sb + 3 * MAT_BYTES + so, g_Vlo + go);
    }
    if (tid < 64) {
        cp8(smem_u32 + MS_OFF_BYTES + st * 512 + tid * 8,
            g_Mb + (size_t)(qbase + tid) * NWORDS + tile * 2);
    }
    cp_commit();
}

__global__ __launch_bounds__(128)
void attn_kernel()
{
    extern __shared__ char dsm[];
    const unsigned smem_u32 = (unsigned)__cvta_generic_to_shared(dsm);
    const unsigned* Msp = (const unsigned*)(dsm + MS_OFF_BYTES);

    const int tid  = threadIdx.x;
    const int w    = tid >> 5;
    const int lane = tid & 31;
    const int g    = lane >> 2;
    const int t    = lane & 3;
    const int b    = blockIdx.z;
    const int h    = blockIdx.y;
    const int qbase = blockIdx.x * 64;
    const size_t bh = ((size_t)b * NH + h) * SEQ;

    stage_tile(smem_u32, 0, bh, qbase, 0, tid);

    unsigned ah[4][4], al[4][4];
    {
        const float* q0p = g_Qh + (bh + qbase + w * 16 + g) * DK;
        const float* q1p = q0p + 8 * DK;
#pragma unroll
        for (int kc = 0; kc < 4; kc++) {
            int d = kc * 16 + t * 2;
            split2(q0p[d],     q0p[d + 1], ah[kc][0], al[kc][0]);
            split2(q1p[d],     q1p[d + 1], ah[kc][1], al[kc][1]);
            split2(q0p[d + 8], q0p[d + 9], ah[kc][2], al[kc][2]);
            split2(q1p[d + 8], q1p[d + 9], ah[kc][3], al[kc][3]);
        }
    }

    float o[8][4];
#pragma unroll
    for (int nt = 0; nt < 8; nt++)
#pragma unroll
        for (int i = 0; i < 4; i++) o[nt][i] = 0.f;
    float mrow0 = -1e30f, mrow1 = -1e30f, lsum0 = 0.f, lsum1 = 0.f;

    const unsigned k_lane = (lane & 7) * KST + ((lane >> 3) & 1) * 8
                          + (lane >> 4) * MAT_U16;
    const unsigned v_lane = ((lane & 7) + ((lane >> 3) & 1) * 8) * KST
                          + (lane >> 4) * MAT_U16;
    const unsigned k_ad = smem_u32 + 2 * k_lane;
    const unsigned v_ad = smem_u32 + 2 * MAT_BYTES + 2 * v_lane;

    for (int tile = 0; tile < NT_T; tile++) {
        const int st = tile & 1;
        __syncthreads();
        if (tile + 1 < NT_T) {
            stage_tile(smem_u32, st ^ 1, bh, qbase, tile + 1, tid);
            cp_wait<1>();
        } else {
            cp_wait<0>();
        }
        __syncthreads();

        const unsigned kst_ad = k_ad + st * STG_BYTES;
        const unsigned vst_ad = v_ad + st * STG_BYTES;

        float s[8][4];
#pragma unroll
        for (int nt = 0; nt < 8; nt++) {
            float c[4] = {0.f, 0.f, 0.f, 0.f};
#pragma unroll
            for (int kc = 0; kc < 4; kc++) {
                unsigned bh0, bh1, bl0, bl1;
                ldsm_x4(bh0, bh1, bl0, bl1,
                        kst_ad + 2 * (nt * 8 * KST + kc * 16));
                mma_bf16(c, al[kc], bh0, bh1);
                mma_bf16(c, ah[kc], bl0, bl1);
                mma_bf16(c, ah[kc], bh0, bh1);
            }
            s[nt][0] = c[0]; s[nt][1] = c[1]; s[nt][2] = c[2]; s[nt][3] = c[3];
        }

        {
            int row0 = w * 16 + g;
            const unsigned* ms = Msp + st * 128;
            unsigned long long M0 = (unsigned long long)ms[row0 * 2]
                                  | ((unsigned long long)ms[row0 * 2 + 1] << 32);
            unsigned long long M1 = (unsigned long long)ms[(row0 + 8) * 2]
                                  | ((unsigned long long)ms[(row0 + 8) * 2 + 1] << 32);
            float rmax0 = -1e30f, rmax1 = -1e30f;
#pragma unroll
            for (int nt = 0; nt < 8; nt++) {
                unsigned sh = nt * 8 + t * 2;
                unsigned b0 = (unsigned)(M0 >> sh);
                unsigned b1 = (unsigned)(M1 >> sh);
                s[nt][0] = (b0 & 1u) ? s[nt][0] * 0.125f : -1e9f;
                s[nt][1] = (b0 & 2u) ? s[nt][1] * 0.125f : -1e9f;
                s[nt][2] = (b1 & 1u) ? s[nt][2] * 0.125f : -1e9f;
                s[nt][3] = (b1 & 2u) ? s[nt][3] * 0.125f : -1e9f;
                rmax0 = fmaxf(rmax0, fmaxf(s[nt][0], s[nt][1]));
                rmax1 = fmaxf(rmax1, fmaxf(s[nt][2], s[nt][3]));
            }
            rmax0 = fmaxf(rmax0, __shfl_xor_sync(0xffffffffu, rmax0, 1));
            rmax0 = fmaxf(rmax0, __shfl_xor_sync(0xffffffffu, rmax0, 2));
            rmax1 = fmaxf(rmax1, __shfl_xor_sync(0xffffffffu, rmax1, 1));
            rmax1 = fmaxf(rmax1, __shfl_xor_sync(0xffffffffu, rmax1, 2));

            float mnew0 = fmaxf(mrow0, rmax0);
            float mnew1 = fmaxf(mrow1, rmax1);
            float corr0 = __expf(mrow0 - mnew0);
            float corr1 = __expf(mrow1 - mnew1);
            mrow0 = mnew0; mrow1 = mnew1;

            float sum0 = 0.f, sum1 = 0.f;
#pragma unroll
            for (int nt = 0; nt < 8; nt++) {
                s[nt][0] = __expf(s[nt][0] - mnew0);
                s[nt][1] = __expf(s[nt][1] - mnew0);
                s[nt][2] = __expf(s[nt][2] - mnew1);
                s[nt][3] = __expf(s[nt][3] - mnew1);
                sum0 += s[nt][0] + s[nt][1];
                sum1 += s[nt][2] + s[nt][3];
            }
            sum0 += __shfl_xor_sync(0xffffffffu, sum0, 1);
            sum0 += __shfl_xor_sync(0xffffffffu, sum0, 2);
            sum1 += __shfl_xor_sync(0xffffffffu, sum1, 1);
            sum1 += __shfl_xor_sync(0xffffffffu, sum1, 2);
            lsum0 = lsum0 * corr0 + sum0;
            lsum1 = lsum1 * corr1 + sum1;

#pragma unroll
            for (int nt = 0; nt < 8; nt++) {
                o[nt][0] *= corr0; o[nt][1] *= corr0;
                o[nt][2] *= corr1; o[nt][3] *= corr1;
            }
        }

#pragma unroll
        for (int kc = 0; kc < 4; kc++) {
            unsigned ph[4], pl[4];
            split2(s[2 * kc][0],     s[2 * kc][1],     ph[0], pl[0]);
            split2(s[2 * kc][2],     s[2 * kc][3],     ph[1], pl[1]);
            split2(s[2 * kc + 1][0], s[2 * kc + 1][1], ph[2], pl[2]);
            split2(s[2 * kc + 1][2], s[2 * kc + 1][3], ph[3], pl[3]);
#pragma unroll
            for (int nt = 0; nt < 8; nt++) {
                unsigned vh0, vh1, vl0, vl1;
                ldsm_x4_t(vh0, vh1, vl0, vl1,
                          vst_ad + 2 * (kc * 16 * KST + nt * 8));
                mma_bf16(o[nt], pl, vh0, vh1);
                mma_bf16(o[nt], ph, vl0, vl1);
                mma_bf16(o[nt], ph, vh0, vh1);
            }
        }
    }

    // ---- epilogue: normalize, split, write bf16 hi/lo concat layout ----
    float inv0 = 1.0f / lsum0;
    float inv1 = 1.0f / lsum1;
    int q0 = qbase + w * 16 + g;
    size_t base0 = ((size_t)b * SEQ + q0) * D_MODEL + h * DK;
    size_t base1 = base0 + 8 * (size_t)D_MODEL;
#pragma unroll
    for (int nt = 0; nt < 8; nt++) {
        unsigned hi, lo;
        split2(o[nt][0] * inv0, o[nt][1] * inv0, hi, lo);
        *(unsigned*)&g_Ohi[base0 + nt * 8 + t * 2] = hi;
        *(unsigned*)&g_Olo[base0 + nt * 8 + t * 2] = lo;
        split2(o[nt][2] * inv1, o[nt][3] * inv1, hi, lo);
        *(unsigned*)&g_Ohi[base1 + nt * 8 + t * 2] = hi;
        *(unsigned*)&g_Olo[base1 + nt * 8 + t * 2] = lo;
    }
}

// ---------------------------------------------------------------------------

extern "C" void kernel_launch(void* const* d_in, const int* in_sizes, int n_in,
                              void* d_out, int out_size)
{
    (void)in_sizes; (void)n_in; (void)out_size;
    const float* q    = (const float*)d_in[0];
    const float* k    = (const float*)d_in[1];
    const float* v    = (const float*)d_in[2];
    const int*   mask = (const int*)  d_in[3];
    const float* Wq   = (const float*)d_in[4];
    const float* bq   = (const float*)d_in[5];
    const float* Wk   = (const float*)d_in[6];
    const float* bk   = (const float*)d_in[7];
    const float* Wv   = (const float*)d_in[8];
    const float* bv   = (const float*)d_in[9];
    const float* Wo   = (const float*)d_in[10];
    const float* bo   = (const float*)d_in[11];
    float* out = (float*)d_out;

    float *Qh;
    uint16_t *Inhi, *Inlo, *Whi, *Wlo, *Khi, *Klo, *Vhi, *Vlo, *Ohi, *Olo;
    cudaGetSymbolAddress((void**)&Qh,   g_Qh);
    cudaGetSymbolAddress((void**)&Inhi, g_Inhi);
    cudaGetSymbolAddress((void**)&Inlo, g_Inlo);
    cudaGetSymbolAddress((void**)&Whi,  g_Whi);
    cudaGetSymbolAddress((void**)&Wlo,  g_Wlo);
    cudaGetSymbolAddress((void**)&Khi,  g_Khi);
    cudaGetSymbolAddress((void**)&Klo,  g_Klo);
    cudaGetSymbolAddress((void**)&Vhi,  g_Vhi);
    cudaGetSymbolAddress((void**)&Vlo,  g_Vlo);
    cudaGetSymbolAddress((void**)&Ohi,  g_Ohi);
    cudaGetSymbolAddress((void**)&Olo,  g_Olo);

    cudaFuncSetAttribute(attn_kernel,
                         cudaFuncAttributeMaxDynamicSharedMemorySize,
                         ATTN_SMEM);
    cudaFuncSetAttribute(proj_kernel,
                         cudaFuncAttributeMaxDynamicSharedMemorySize,
                         PROJ_SMEM);

    mask_bits_kernel<<<SEQ * NWORDS / 256, 256>>>(mask);
    split_in_kernel<<<dim3(IN_SZ / 1024, 3), 256>>>(q, k, v);
    split_w_kernel<<<dim3(W_SZ / 1024, 4), 256>>>(Wq, Wk, Wv, Wo);

    dim3 proj_grid(D_MODEL / PBN, MTOT / PBM);   // (8, 64)
    proj_kernel<<<proj_grid, 128, PROJ_SMEM>>>(
        Inhi, Inlo, Whi, Wlo, bq, Qh, nullptr, nullptr, 1);
    proj_kernel<<<proj_grid, 128, PROJ_SMEM>>>(
        Inhi + IN_SZ, Inlo + IN_SZ, Whi + W_SZ, Wlo + W_SZ,
        bk, nullptr, Khi, Klo, 2);
    proj_kernel<<<proj_grid, 128, PROJ_SMEM>>>(
        Inhi + 2 * IN_SZ, Inlo + 2 * IN_SZ, Whi + 2 * W_SZ, Wlo + 2 * W_SZ,
        bv, nullptr, Vhi, Vlo, 2);

    dim3 attn_grid(SEQ / 64, NH, BATCH);         // (32, 8, 4)
    attn_kernel<<<attn_grid, 128, ATTN_SMEM>>>();

    proj_kernel<<<proj_grid, 128, PROJ_SMEM>>>(
        Ohi, Olo, Whi + 3 * W_SZ, Wlo + 3 * W_SZ, bo, out, nullptr, nullptr, 0);
}

// round 13
// speedup vs baseline: 4.9436x; 1.1652x over previous
#include <cuda_runtime.h>
#include <cuda_bf16.h>
#include <math.h>
#include <stdint.h>

#define D_MODEL 512
#define NH      8
#define DK      64
#define BATCH   4
#define SEQ     2048
#define MTOT    (BATCH * SEQ)   // 8192
#define NWORDS  (SEQ / 32)      // 64 mask words per row
#define IN_SZ   ((size_t)MTOT * D_MODEL)     // 4194304
#define W_SZ    ((size_t)D_MODEL * D_MODEL)  // 262144

// Scratch (allocation-free rule: __device__ globals)
__device__ float g_Qh[IN_SZ];
__device__ __align__(16) uint16_t g_Inhi[3 * IN_SZ];
__device__ __align__(16) uint16_t g_Inlo[3 * IN_SZ];
__device__ __align__(16) uint16_t g_Whi[4 * W_SZ];
__device__ __align__(16) uint16_t g_Wlo[4 * W_SZ];
__device__ __align__(16) uint16_t g_Khi[IN_SZ];   // f16 hi/lo
__device__ __align__(16) uint16_t g_Klo[IN_SZ];
__device__ __align__(16) uint16_t g_Vhi[IN_SZ];   // f16 hi/lo
__device__ __align__(16) uint16_t g_Vlo[IN_SZ];
__device__ __align__(16) uint16_t g_Ohi[IN_SZ];   // bf16 hi/lo (O-proj operand)
__device__ __align__(16) uint16_t g_Olo[IN_SZ];
__device__ __align__(16) unsigned g_Mb[(size_t)SEQ * NWORDS];

// ---------------------------------------------------------------------------
// bf16 helpers: pack2(e0,e1): e0 -> low half, e1 -> high half
// ---------------------------------------------------------------------------
__device__ __forceinline__ unsigned pack2(float e0, float e1) {
    unsigned r;
    asm("cvt.rn.bf16x2.f32 %0, %1, %2;" : "=r"(r) : "f"(e1), "f"(e0));
    return r;
}
__device__ __forceinline__ void split2(float x0, float x1,
                                       unsigned& hi, unsigned& lo) {
    hi = pack2(x0, x1);
    float h0 = __uint_as_float(hi << 16);
    float h1 = __uint_as_float(hi & 0xffff0000u);
    lo = pack2(x0 - h0, x1 - h1);
}

// ---------------------------------------------------------------------------
// f16 helpers
// ---------------------------------------------------------------------------
__device__ __forceinline__ unsigned pack2h(float e0, float e1) {
    unsigned r;
    asm("cvt.rn.f16x2.f32 %0, %1, %2;" : "=r"(r) : "f"(e1), "f"(e0));
    return r;
}
__device__ __forceinline__ void split2h(float x0, float x1,
                                        unsigned& hi, unsigned& lo) {
    hi = pack2h(x0, x1);
    float h0, h1;
    asm("{.reg .f16 a,b;\n\t mov.b32 {a,b}, %2;\n\t"
        "cvt.f32.f16 %0, a;\n\t cvt.f32.f16 %1, b;}"
        : "=f"(h0), "=f"(h1) : "r"(hi));
    lo = pack2h(x0 - h0, x1 - h1);
}
__device__ __forceinline__ unsigned ex2h2(unsigned d) {
    unsigned r;
    asm("ex2.approx.f16x2 %0, %1;" : "=r"(r) : "r"(d));
    return r;
}

// m16n8k16 MMAs, D += A*B
__device__ __forceinline__ void mma_bf16(float c[4], const unsigned a[4],
                                         unsigned b0, unsigned b1) {
    asm("mma.sync.aligned.m16n8k16.row.col.f32.bf16.bf16.f32 "
        "{%0,%1,%2,%3}, {%4,%5,%6,%7}, {%8,%9}, {%0,%1,%2,%3};"
        : "+f"(c[0]), "+f"(c[1]), "+f"(c[2]), "+f"(c[3])
        : "r"(a[0]), "r"(a[1]), "r"(a[2]), "r"(a[3]), "r"(b0), "r"(b1));
}
__device__ __forceinline__ void mma_f16(float c[4], const unsigned a[4],
                                        unsigned b0, unsigned b1) {
    asm("mma.sync.aligned.m16n8k16.row.col.f32.f16.f16.f32 "
        "{%0,%1,%2,%3}, {%4,%5,%6,%7}, {%8,%9}, {%0,%1,%2,%3};"
        : "+f"(c[0]), "+f"(c[1]), "+f"(c[2]), "+f"(c[3])
        : "r"(a[0]), "r"(a[1]), "r"(a[2]), "r"(a[3]), "r"(b0), "r"(b1));
}

__device__ __forceinline__ void ldsm_x4(unsigned& r0, unsigned& r1,
                                        unsigned& r2, unsigned& r3,
                                        unsigned addr) {
    asm volatile("ldmatrix.sync.aligned.m8n8.x4.shared.b16 {%0,%1,%2,%3}, [%4];"
                 : "=r"(r0), "=r"(r1), "=r"(r2), "=r"(r3) : "r"(addr));
}
__device__ __forceinline__ void ldsm_x4_t(unsigned& r0, unsigned& r1,
                                          unsigned& r2, unsigned& r3,
                                          unsigned addr) {
    asm volatile("ldmatrix.sync.aligned.m8n8.x4.trans.shared.b16 {%0,%1,%2,%3}, [%4];"
                 : "=r"(r0), "=r"(r1), "=r"(r2), "=r"(r3) : "r"(addr));
}

// cp.async helpers
__device__ __forceinline__ void cp16(unsigned saddr, const void* g) {
    asm volatile("cp.async.cg.shared.global [%0], [%1], 16;"
                 :: "r"(saddr), "l"(g));
}
__device__ __forceinline__ void cp8(unsigned saddr, const void* g) {
    asm volatile("cp.async.ca.shared.global [%0], [%1], 8;"
                 :: "r"(saddr), "l"(g));
}
__device__ __forceinline__ void cp_commit() {
    asm volatile("cp.async.commit_group;");
}
template<int N> __device__ __forceinline__ void cp_wait() {
    asm volatile("cp.async.wait_group %0;" :: "n"(N));
}

// ---------------------------------------------------------------------------
// Prep kernels
// ---------------------------------------------------------------------------
__global__ __launch_bounds__(256)
void mask_bits_kernel(const int* __restrict__ mask)
{
    int w = blockIdx.x * 256 + threadIdx.x;
    const int* mp = mask + (size_t)w * 32;
    unsigned bits = 0;
#pragma unroll
    for (int j = 0; j < 8; j++) {
        int4 m = *(const int4*)(mp + 4 * j);
        bits |= (unsigned)(m.x != 0) << (4 * j);
        bits |= (unsigned)(m.y != 0) << (4 * j + 1);
        bits |= (unsigned)(m.z != 0) << (4 * j + 2);
        bits |= (unsigned)(m.w != 0) << (4 * j + 3);
    }
    g_Mb[w] = bits;
}

__global__ __launch_bounds__(256)
void split_in_kernel(const float* __restrict__ q,
                     const float* __restrict__ k,
                     const float* __restrict__ v)
{
    int which = blockIdx.y;
    const float* src = (which == 0) ? q : (which == 1) ? k : v;
    size_t i = ((size_t)blockIdx.x * 256 + threadIdx.x) * 4;
    float4 x = *(const float4*)(src + i);
    unsigned h01, l01, h23, l23;
    split2(x.x, x.y, h01, l01);
    split2(x.z, x.w, h23, l23);
    size_t o = (size_t)which * IN_SZ + i;
    *(uint2*)&g_Inhi[o] = make_uint2(h01, h23);
    *(uint2*)&g_Inlo[o] = make_uint2(l01, l23);
}

__global__ __launch_bounds__(256)
void split_w_kernel(const float* __restrict__ w0,
                    const float* __restrict__ w1,
                    const float* __restrict__ w2,
                    const float* __restrict__ w3)
{
    int which = blockIdx.y;
    const float* src = (which == 0) ? w0 : (which == 1) ? w1
                     : (which == 2) ? w2 : w3;
    size_t i = ((size_t)blockIdx.x * 256 + threadIdx.x) * 4;
    float4 x = *(const float4*)(src + i);
    unsigned h01, l01, h23, l23;
    split2(x.x, x.y, h01, l01);
    split2(x.z, x.w, h23, l23);
    size_t o = (size_t)which * W_SZ + i;
    *(uint2*)&g_Whi[o] = make_uint2(h01, h23);
    *(uint2*)&g_Wlo[o] = make_uint2(l01, l23);
}

// ---------------------------------------------------------------------------
// Projection GEMM: pre-split bf16 hi/lo operands, cp.async double buffer.
// mode 0: f32 [M,512]; mode 1: f32 head layout; mode 2: f16 hi/lo head layout
// ---------------------------------------------------------------------------
#define PBM  128
#define PBN  64
#define PBK  32
#define PKST 40
#define P_STG_U16   (2 * PBM * PKST + 2 * PBN * PKST)   // 15360
#define P_STG_BYTES (P_STG_U16 * 2)                      // 30720
#define PROJ_SMEM   (2 * P_STG_BYTES)                    // 61440
#define NKI  (D_MODEL / PBK)                             // 16

__device__ __forceinline__ void proj_stage(unsigned sb,
        const uint16_t* __restrict__ Ahi, const uint16_t* __restrict__ Alo,
        const uint16_t* __restrict__ Whi, const uint16_t* __restrict__ Wlo,
        int m0, int n0, int k0, int tid)
{
#pragma unroll
    for (int l = 0; l < 4; l++) {
        int v   = l * 128 + tid;
        int row = v >> 2, cb = v & 3;
        size_t   go = (size_t)(m0 + row) * D_MODEL + k0 + cb * 8;
        unsigned so = 2u * (row * PKST + cb * 8);
        cp16(sb + so,                     Ahi + go);
        cp16(sb + 2u * PBM * PKST + so,   Alo + go);
    }
#pragma unroll
    for (int l = 0; l < 2; l++) {
        int v   = l * 128 + tid;
        int row = v >> 2, cb = v & 3;
        size_t   go = (size_t)(n0 + row) * D_MODEL + k0 + cb * 8;
        unsigned so = 2u * (row * PKST + cb * 8);
        cp16(sb + 4u * PBM * PKST + so,                     Whi + go);
        cp16(sb + 4u * PBM * PKST + 2u * PBN * PKST + so,   Wlo + go);
    }
    cp_commit();
}

__global__ __launch_bounds__(128)
void proj_kernel(const uint16_t* __restrict__ Ahi,
                 const uint16_t* __restrict__ Alo,
                 const uint16_t* __restrict__ Whi,
                 const uint16_t* __restrict__ Wlo,
                 const float* __restrict__ bias,
                 float* __restrict__ Yf,
                 uint16_t* __restrict__ Yhi,
                 uint16_t* __restrict__ Ylo,
                 int mode)
{
    extern __shared__ char psm[];
    const unsigned sbase = (unsigned)__cvta_generic_to_shared(psm);

    const int tid  = threadIdx.x;
    const int lane = tid & 31;
    const int w    = tid >> 5;
    const int wm   = w & 1;
    const int wn   = w >> 1;
    const int g    = lane >> 2;
    const int t    = lane & 3;
    const int m0   = blockIdx.y * PBM;
    const int n0   = blockIdx.x * PBN;

    float c[4][4][4];
#pragma unroll
    for (int i = 0; i < 4; i++)
#pragma unroll
        for (int j = 0; j < 4; j++)
#pragma unroll
            for (int q = 0; q < 4; q++) c[i][j][q] = 0.f;

    const unsigned a_lane = (wm * 64 + ((lane >> 3) & 1) * 8 + (lane & 7)) * PKST
                          + (lane >> 4) * 8;
    const unsigned b_lane = (wn * 32 + (lane & 7)) * PKST
                          + ((lane >> 3) & 1) * 8
                          + (lane >> 4) * (PBN * PKST);
    const unsigned a_hi_off = 2 * a_lane;
    const unsigned a_lo_off = a_hi_off + 2 * (PBM * PKST);
    const unsigned b_off    = 4 * PBM * PKST + 2 * b_lane;

    proj_stage(sbase, Ahi, Alo, Whi, Wlo, m0, n0, 0, tid);

    for (int ki = 0; ki < NKI; ki++) {
        const int st = ki & 1;
        __syncthreads();
        if (ki + 1 < NKI) {
            proj_stage(sbase + (st ^ 1) * P_STG_BYTES,
                       Ahi, Alo, Whi, Wlo, m0, n0, (ki + 1) * PBK, tid);
            cp_wait<1>();
        } else {
            cp_wait<0>();
        }
        __syncthreads();

        const unsigned sb = sbase + st * P_STG_BYTES;
#pragma unroll
        for (int kk = 0; kk < 2; kk++) {
            unsigned ah[4][4], al[4][4];
#pragma unroll
            for (int mt = 0; mt < 4; mt++) {
                unsigned off = 2 * (mt * 16 * PKST + kk * 16);
                ldsm_x4(ah[mt][0], ah[mt][1], ah[mt][2], ah[mt][3],
                        sb + a_hi_off + off);
                ldsm_x4(al[mt][0], al[mt][1], al[mt][2], al[mt][3],
                        sb + a_lo_off + off);
            }
#pragma unroll
            for (int nt = 0; nt < 4; nt++) {
                unsigned bh0, bh1, bl0, bl1;
                ldsm_x4(bh0, bh1, bl0, bl1,
                        sb + b_off + 2 * (nt * 8 * PKST + kk * 16));
#pragma unroll
                for (int mt = 0; mt < 4; mt++) {
                    mma_bf16(c[mt][nt], al[mt], bh0, bh1);
                    mma_bf16(c[mt][nt], ah[mt], bl0, bl1);
                    mma_bf16(c[mt][nt], ah[mt], bh0, bh1);
                }
            }
        }
    }

    // ---- epilogue ----
#pragma unroll
    for (int mt = 0; mt < 4; mt++) {
#pragma unroll
        for (int nt = 0; nt < 4; nt++) {
            int n = n0 + wn * 32 + nt * 8 + t * 2;
            float2 bi = *(const float2*)(bias + n);
#pragma unroll
            for (int half = 0; half < 2; half++) {
                int m = m0 + wm * 64 + mt * 16 + g + half * 8;
                float2 val = make_float2(c[mt][nt][half * 2]     + bi.x,
                                         c[mt][nt][half * 2 + 1] + bi.y);
                if (mode == 0) {
                    *(float2*)&Yf[(size_t)m * D_MODEL + n] = val;
                } else {
                    int bb = m >> 11;
                    int s  = m & (SEQ - 1);
                    int hh = n >> 6;
                    int d  = n & (DK - 1);
                    size_t idx = (((size_t)(bb * NH + hh) * SEQ) + s) * DK + d;
                    if (mode == 1) {
                        *(float2*)&Yf[idx] = val;
                    } else {
                        unsigned hi, lo;
                        split2h(val.x, val.y, hi, lo);   // f16 hi/lo for attn
                        *(unsigned*)&Yhi[idx] = hi;
                        *(unsigned*)&Ylo[idx] = lo;
                    }
                }
            }
        }
    }
}

// ---------------------------------------------------------------------------
// Flash attention, f16 path: QK 3-term f16 MMA; softmax in log2 domain with
// ex2.approx.f16x2 (outputs ARE the PV A-fragments); PV = p*Vhi + p*Vlo;
// lsum via ones-column MMA accumulator.
// ---------------------------------------------------------------------------
#define BKT   64
#define NT_T  (SEQ / BKT)          // 32 tiles
#define KST   72
#define MAT_U16   (64 * KST)       // 4608
#define MAT_BYTES (MAT_U16 * 2)    // 9216
#define STG_BYTES (4 * MAT_BYTES)  // 36864
#define MS_OFF_BYTES (2 * STG_BYTES)
#define ATTN_SMEM (MS_OFF_BYTES + 2 * 128 * 4)   // 74752
#define ONES_H2  0x3C003C00u       // f16x2 {1.0, 1.0}
#define SC2      0.18033688f       // 0.125 * log2(e)

__device__ __forceinline__ void stage_tile(unsigned smem_u32, int st,
                                           size_t bh, int qbase, int tile,
                                           int tid)
{
    const int k0 = tile * BKT;
    const unsigned sb = smem_u32 + st * STG_BYTES;
#pragma unroll
    for (int l = 0; l < 4; l++) {
        int cc  = tid + l * 128;
        int row = cc >> 3;
        int col = cc & 7;
        size_t  go = (size_t)(bh + k0 + row) * DK + col * 8;
        unsigned so = 2 * (row * KST + col * 8);
        cp16(sb + so,                 g_Khi + go);
        cp16(sb + MAT_BYTES + so,     g_Klo + go);
        cp16(sb + 2 * MAT_BYTES + so, g_Vhi + go);
        cp16(sb + 3 * MAT_BYTES + so, g_Vlo + go);
    }
    if (tid < 64) {
        cp8(smem_u32 + MS_OFF_BYTES + st * 512 + tid * 8,
            g_Mb + (size_t)(qbase + tid) * NWORDS + tile * 2);
    }
    cp_commit();
}

__global__ __launch_bounds__(128)
void attn_kernel()
{
    extern __shared__ char dsm[];
    const unsigned smem_u32 = (unsigned)__cvta_generic_to_shared(dsm);
    const unsigned* Msp = (const unsigned*)(dsm + MS_OFF_BYTES);

    const int tid  = threadIdx.x;
    const int w    = tid >> 5;
    const int lane = tid & 31;
    const int g    = lane >> 2;
    const int t    = lane & 3;
    const int b    = blockIdx.z;
    const int h    = blockIdx.y;
    const int qbase = blockIdx.x * 64;
    const size_t bh = ((size_t)b * NH + h) * SEQ;

    stage_tile(smem_u32, 0, bh, qbase, 0, tid);

    // ---- Q fragments (f16 hi/lo) once ----
    unsigned ah[4][4], al[4][4];
    {
        const float* q0p = g_Qh + (bh + qbase + w * 16 + g) * DK;
        const float* q1p = q0p + 8 * DK;
#pragma unroll
        for (int kc = 0; kc < 4; kc++) {
            int d = kc * 16 + t * 2;
            split2h(q0p[d],     q0p[d + 1], ah[kc][0], al[kc][0]);
            split2h(q1p[d],     q1p[d + 1], ah[kc][1], al[kc][1]);
            split2h(q0p[d + 8], q0p[d + 9], ah[kc][2], al[kc][2]);
            split2h(q1p[d + 8], q1p[d + 9], ah[kc][3], al[kc][3]);
        }
    }

    float o[8][4];
#pragma unroll
    for (int nt = 0; nt < 8; nt++)
#pragma unroll
        for (int i = 0; i < 4; i++) o[nt][i] = 0.f;
    float osum[4] = {0.f, 0.f, 0.f, 0.f};   // ones-MMA lsum accumulator
    float mrow0 = -1e30f, mrow1 = -1e30f;

    const unsigned k_lane = (lane & 7) * KST + ((lane >> 3) & 1) * 8
                          + (lane >> 4) * MAT_U16;
    const unsigned v_lane = ((lane & 7) + ((lane >> 3) & 1) * 8) * KST
                          + (lane >> 4) * MAT_U16;
    const unsigned k_ad = smem_u32 + 2 * k_lane;
    const unsigned v_ad = smem_u32 + 2 * MAT_BYTES + 2 * v_lane;

    for (int tile = 0; tile < NT_T; tile++) {
        const int st = tile & 1;
        __syncthreads();
        if (tile + 1 < NT_T) {
            stage_tile(smem_u32, st ^ 1, bh, qbase, tile + 1, tid);
            cp_wait<1>();
        } else {
            cp_wait<0>();
        }
        __syncthreads();

        const unsigned kst_ad = k_ad + st * STG_BYTES;
        const unsigned vst_ad = v_ad + st * STG_BYTES;

        // ---- S = Q @ K^T (3-term f16) ----
        float s[8][4];
#pragma unroll
        for (int nt = 0; nt < 8; nt++) {
            float c[4] = {0.f, 0.f, 0.f, 0.f};
#pragma unroll
            for (int kc = 0; kc < 4; kc++) {
                unsigned bh0, bh1, bl0, bl1;
                ldsm_x4(bh0, bh1, bl0, bl1,
                        kst_ad + 2 * (nt * 8 * KST + kc * 16));
                mma_f16(c, al[kc], bh0, bh1);
                mma_f16(c, ah[kc], bl0, bl1);
                mma_f16(c, ah[kc], bh0, bh1);
            }
            s[nt][0] = c[0]; s[nt][1] = c[1]; s[nt][2] = c[2]; s[nt][3] = c[3];
        }

        // ---- mask + scale (log2 domain) + online softmax ----
        unsigned pf[8][2];
        {
            int row0 = w * 16 + g;
            const unsigned* ms = Msp + st * 128;
            unsigned long long M0 = (unsigned long long)ms[row0 * 2]
                                  | ((unsigned long long)ms[row0 * 2 + 1] << 32);
            unsigned long long M1 = (unsigned long long)ms[(row0 + 8) * 2]
                                  | ((unsigned long long)ms[(row0 + 8) * 2 + 1] << 32);
            float rmax0 = -1e30f, rmax1 = -1e30f;
#pragma unroll
            for (int nt = 0; nt < 8; nt++) {
                unsigned sh = nt * 8 + t * 2;
                unsigned b0 = (unsigned)(M0 >> sh);
                unsigned b1 = (unsigned)(M1 >> sh);
                s[nt][0] = (b0 & 1u) ? s[nt][0] * SC2 : -1e9f;
                s[nt][1] = (b0 & 2u) ? s[nt][1] * SC2 : -1e9f;
                s[nt][2] = (b1 & 1u) ? s[nt][2] * SC2 : -1e9f;
                s[nt][3] = (b1 & 2u) ? s[nt][3] * SC2 : -1e9f;
                rmax0 = fmaxf(rmax0, fmaxf(s[nt][0], s[nt][1]));
                rmax1 = fmaxf(rmax1, fmaxf(s[nt][2], s[nt][3]));
            }
            rmax0 = fmaxf(rmax0, __shfl_xor_sync(0xffffffffu, rmax0, 1));
            rmax0 = fmaxf(rmax0, __shfl_xor_sync(0xffffffffu, rmax0, 2));
            rmax1 = fmaxf(rmax1, __shfl_xor_sync(0xffffffffu, rmax1, 1));
            rmax1 = fmaxf(rmax1, __shfl_xor_sync(0xffffffffu, rmax1, 2));

            float mnew0 = fmaxf(mrow0, rmax0);
            float mnew1 = fmaxf(mrow1, rmax1);
            float corr0 = exp2f(mrow0 - mnew0);
            float corr1 = exp2f(mrow1 - mnew1);
            mrow0 = mnew0; mrow1 = mnew1;

            // p = 2^(s - m) via f16x2 ex2; outputs are PV A-fragments
#pragma unroll
            for (int nt = 0; nt < 8; nt++) {
                pf[nt][0] = ex2h2(pack2h(s[nt][0] - mnew0, s[nt][1] - mnew0));
                pf[nt][1] = ex2h2(pack2h(s[nt][2] - mnew1, s[nt][3] - mnew1));
            }

            // rescale O and lsum accumulators
#pragma unroll
            for (int nt = 0; nt < 8; nt++) {
                o[nt][0] *= corr0; o[nt][1] *= corr0;
                o[nt][2] *= corr1; o[nt][3] *= corr1;
            }
            osum[0] *= corr0; osum[1] *= corr0;
            osum[2] *= corr1; osum[3] *= corr1;
        }

        // ---- O += P @ V ; lsum via ones-column MMA ----
#pragma unroll
        for (int kc = 0; kc < 4; kc++) {
            unsigned a[4] = { pf[2 * kc][0],     pf[2 * kc][1],
                              pf[2 * kc + 1][0], pf[2 * kc + 1][1] };
            mma_f16(osum, a, ONES_H2, ONES_H2);
#pragma unroll
            for (int nt = 0; nt < 8; nt++) {
                unsigned vh0, vh1, vl0, vl1;
                ldsm_x4_t(vh0, vh1, vl0, vl1,
                          vst_ad + 2 * (kc * 16 * KST + nt * 8));
                mma_f16(o[nt], a, vh0, vh1);
                mma_f16(o[nt], a, vl0, vl1);
            }
        }
    }

    // ---- epilogue: normalize, split (bf16 for O-proj), write ----
    float inv0 = 1.0f / osum[0];
    float inv1 = 1.0f / osum[2];
    int q0 = qbase + w * 16 + g;
    size_t base0 = ((size_t)b * SEQ + q0) * D_MODEL + h * DK;
    size_t base1 = base0 + 8 * (size_t)D_MODEL;
#pragma unroll
    for (int nt = 0; nt < 8; nt++) {
        unsigned hi, lo;
        split2(o[nt][0] * inv0, o[nt][1] * inv0, hi, lo);
        *(unsigned*)&g_Ohi[base0 + nt * 8 + t * 2] = hi;
        *(unsigned*)&g_Olo[base0 + nt * 8 + t * 2] = lo;
        split2(o[nt][2] * inv1, o[nt][3] * inv1, hi, lo);
        *(unsigned*)&g_Ohi[base1 + nt * 8 + t * 2] = hi;
        *(unsigned*)&g_Olo[base1 + nt * 8 + t * 2] = lo;
    }
}

// ---------------------------------------------------------------------------

extern "C" void kernel_launch(void* const* d_in, const int* in_sizes, int n_in,
                              void* d_out, int out_size)
{
    (void)in_sizes; (void)n_in; (void)out_size;
    const float* q    = (const float*)d_in[0];
    const float* k    = (const float*)d_in[1];
    const float* v    = (const float*)d_in[2];
    const int*   mask = (const int*)  d_in[3];
    const float* Wq   = (const float*)d_in[4];
    const float* bq   = (const float*)d_in[5];
    const float* Wk   = (const float*)d_in[6];
    const float* bk   = (const float*)d_in[7];
    const float* Wv   = (const float*)d_in[8];
    const float* bv   = (const float*)d_in[9];
    const float* Wo   = (const float*)d_in[10];
    const float* bo   = (const float*)d_in[11];
    float* out = (float*)d_out;

    float *Qh;
    uint16_t *Inhi, *Inlo, *Whi, *Wlo, *Khi, *Klo, *Vhi, *Vlo, *Ohi, *Olo;
    cudaGetSymbolAddress((void**)&Qh,   g_Qh);
    cudaGetSymbolAddress((void**)&Inhi, g_Inhi);
    cudaGetSymbolAddress((void**)&Inlo, g_Inlo);
    cudaGetSymbolAddress((void**)&Whi,  g_Whi);
    cudaGetSymbolAddress((void**)&Wlo,  g_Wlo);
    cudaGetSymbolAddress((void**)&Khi,  g_Khi);
    cudaGetSymbolAddress((void**)&Klo,  g_Klo);
    cudaGetSymbolAddress((void**)&Vhi,  g_Vhi);
    cudaGetSymbolAddress((void**)&Vlo,  g_Vlo);
    cudaGetSymbolAddress((void**)&Ohi,  g_Ohi);
    cudaGetSymbolAddress((void**)&Olo,  g_Olo);

    cudaFuncSetAttribute(attn_kernel,
                         cudaFuncAttributeMaxDynamicSharedMemorySize,
                         ATTN_SMEM);
    cudaFuncSetAttribute(proj_kernel,
                         cudaFuncAttributeMaxDynamicSharedMemorySize,
                         PROJ_SMEM);

    mask_bits_kernel<<<SEQ * NWORDS / 256, 256>>>(mask);
    split_in_kernel<<<dim3(IN_SZ / 1024, 3), 256>>>(q, k, v);
    split_w_kernel<<<dim3(W_SZ / 1024, 4), 256>>>(Wq, Wk, Wv, Wo);

    dim3 proj_grid(D_MODEL / PBN, MTOT / PBM);   // (8, 64)
    proj_kernel<<<proj_grid, 128, PROJ_SMEM>>>(
        Inhi, Inlo, Whi, Wlo, bq, Qh, nullptr, nullptr, 1);
    proj_kernel<<<proj_grid, 128, PROJ_SMEM>>>(
        Inhi + IN_SZ, Inlo + IN_SZ, Whi + W_SZ, Wlo + W_SZ,
        bk, nullptr, Khi, Klo, 2);
    proj_kernel<<<proj_grid, 128, PROJ_SMEM>>>(
        Inhi + 2 * IN_SZ, Inlo + 2 * IN_SZ, Whi + 2 * W_SZ, Wlo + 2 * W_SZ,
        bv, nullptr, Vhi, Vlo, 2);

    dim3 attn_grid(SEQ / 64, NH, BATCH);         // (32, 8, 4)
    attn_kernel<<<attn_grid, 128, ATTN_SMEM>>>();

    proj_kernel<<<proj_grid, 128, PROJ_SMEM>>>(
        Ohi, Olo, Whi + 3 * W_SZ, Wlo + 3 * W_SZ, bo, out, nullptr, nullptr, 0);
}